// round 2
// baseline (speedup 1.0000x reference)
#include <cuda_runtime.h>
#include <math_constants.h>

#define EMBED 1024
#define BATCH 4
#define SEQ 4096
#define NHEAD 16
#define HD 64
#define M_QKV (BATCH*SEQ)        /* 16384 */
#define NPOOL (BATCH*NHEAD)      /* 64 heads total */
#define SP (SEQ/2)               /* 2048 pooled kv/q length */
#define SQ4 (SEQ/4)              /* 1024 final pooled length */

// ---------------- scratch (device globals; no runtime allocation) ----------
__device__ float g_QKV[(size_t)3*M_QKV*EMBED];  // 192 MB
__device__ float g_q[(size_t)NPOOL*SP*HD];      // 32 MB
__device__ float g_k[(size_t)NPOOL*SP*HD];
__device__ float g_v[(size_t)NPOOL*SP*HD];
__device__ float g_A[(size_t)BATCH*SQ4*EMBED];  // 16 MB, already in reshape layout

// ---------------- generic 128x128x16 fp32 GEMM body ------------------------
__device__ __forceinline__ void gemm128(const float* __restrict__ A,
                                        const float* __restrict__ W,
                                        const float* __restrict__ bias,
                                        float* __restrict__ C,
                                        int K, int N)
{
    __shared__ float As[16][128];   // transposed: [k][m]
    __shared__ float Bs[16][128];   // [k][n]
    const int tid = threadIdx.x;
    const int tx = tid & 15, ty = tid >> 4;
    const int bm = blockIdx.y * 128;
    const int bn = blockIdx.x * 128;

    float acc[8][8];
    #pragma unroll
    for (int i = 0; i < 8; i++)
        #pragma unroll
        for (int j = 0; j < 8; j++) acc[i][j] = 0.f;

    for (int k0 = 0; k0 < K; k0 += 16) {
        #pragma unroll
        for (int i = 0; i < 2; i++) {
            int idx = tid + i * 256;
            int r = idx >> 2, c4 = idx & 3;
            float4 v = *(const float4*)(A + (size_t)(bm + r) * K + k0 + c4 * 4);
            As[c4*4+0][r] = v.x; As[c4*4+1][r] = v.y;
            As[c4*4+2][r] = v.z; As[c4*4+3][r] = v.w;
        }
        #pragma unroll
        for (int i = 0; i < 2; i++) {
            int idx = tid + i * 256;
            int r = idx >> 5, c4 = idx & 31;
            *(float4*)&Bs[r][c4*4] = *(const float4*)(W + (size_t)(k0 + r) * N + bn + c4 * 4);
        }
        __syncthreads();
        #pragma unroll
        for (int k = 0; k < 16; k++) {
            float a[8], b[8];
            *(float4*)&a[0] = *(const float4*)&As[k][ty*8];
            *(float4*)&a[4] = *(const float4*)&As[k][ty*8+4];
            *(float4*)&b[0] = *(const float4*)&Bs[k][tx*8];
            *(float4*)&b[4] = *(const float4*)&Bs[k][tx*8+4];
            #pragma unroll
            for (int i = 0; i < 8; i++)
                #pragma unroll
                for (int j = 0; j < 8; j++)
                    acc[i][j] = fmaf(a[i], b[j], acc[i][j]);
        }
        __syncthreads();
    }
    #pragma unroll
    for (int i = 0; i < 8; i++) {
        size_t row = (size_t)(bm + ty*8 + i);
        #pragma unroll
        for (int j4 = 0; j4 < 2; j4++) {
            int col = bn + tx*8 + j4*4;
            float4 v;
            v.x = acc[i][j4*4+0] + bias[col+0];
            v.y = acc[i][j4*4+1] + bias[col+1];
            v.z = acc[i][j4*4+2] + bias[col+2];
            v.w = acc[i][j4*4+3] + bias[col+3];
            *(float4*)(C + row * N + col) = v;
        }
    }
}

// ---------------- kernel 1: QKV projection ---------------------------------
__global__ __launch_bounds__(256, 2)
void qkv_gemm_kernel(const float* __restrict__ x,
                     const float* __restrict__ Wq, const float* __restrict__ Wk,
                     const float* __restrict__ Wv,
                     const float* __restrict__ bq, const float* __restrict__ bk,
                     const float* __restrict__ bv)
{
    int z = blockIdx.z;
    const float* W    = (z == 0) ? Wq : (z == 1) ? Wk : Wv;
    const float* bias = (z == 0) ? bq : (z == 1) ? bk : bv;
    float* C = g_QKV + (size_t)z * M_QKV * EMBED;
    gemm128(x, W, bias, C, EMBED, EMBED);
}

// ---------------- kernel 2: head split + seq maxpool(2) --------------------
__global__ __launch_bounds__(256)
void pool_kernel()
{
    int idx = blockIdx.x * 256 + threadIdx.x;   // 0 .. 3*64*2048*16-1 (= 3*2^21)
    int c4 = idx & 15;
    int sp = (idx >> 4) & 2047;
    int n  = (idx >> 15) & 63;
    int z  = idx >> 21;
    int b = n >> 4, h = n & 15;
    const float* src = g_QKV + (size_t)z * M_QKV * EMBED
                     + (size_t)(b * SEQ + 2 * sp) * EMBED + h * HD + c4 * 4;
    float4 u = *(const float4*)src;
    float4 w = *(const float4*)(src + EMBED);
    float4 r;
    r.x = fmaxf(u.x, w.x); r.y = fmaxf(u.y, w.y);
    r.z = fmaxf(u.z, w.z); r.w = fmaxf(u.w, w.w);
    float* dstbase = (z == 0) ? g_q : (z == 1) ? g_k : g_v;
    *(float4*)(dstbase + ((size_t)n * SP + sp) * HD + c4 * 4) = r;
}

// ---------------- kernel 3: flash attention + final maxpool ----------------
#define LDT 68
__global__ __launch_bounds__(256)
void attn_kernel()
{
    extern __shared__ float sm[];
    float (*Qt)[LDT] = (float(*)[LDT])(sm);             // [d][r], pre-scaled by 1/8
    float (*Kt)[LDT] = (float(*)[LDT])(sm + 64*LDT);    // [d][c]
    float (*Vs)[LDT] = (float(*)[LDT])(sm + 2*64*LDT);  // [k][c]
    float (*Pt)[LDT] = (float(*)[LDT])(sm + 3*64*LDT);  // [k][r]

    const int tid = threadIdx.x;
    const int tx = tid & 15, ty = tid >> 4;
    const int n  = blockIdx.y;          // head (b*16+h)
    const int q0 = blockIdx.x * 64;     // q-tile start in pooled seq

    const float* qb = g_q + ((size_t)n * SP + q0) * HD;
    const float* kb = g_k + (size_t)n * SP * HD;
    const float* vb = g_v + (size_t)n * SP * HD;

    #pragma unroll
    for (int i = 0; i < 4; i++) {
        int idx = tid + i * 256;
        int r = idx >> 4, c4 = idx & 15;
        float4 v = *(const float4*)(qb + r * HD + c4 * 4);
        Qt[c4*4+0][r] = v.x * 0.125f; Qt[c4*4+1][r] = v.y * 0.125f;
        Qt[c4*4+2][r] = v.z * 0.125f; Qt[c4*4+3][r] = v.w * 0.125f;
    }

    float m_i[4], l_i[4], O[4][4];
    #pragma unroll
    for (int i = 0; i < 4; i++) {
        m_i[i] = -CUDART_INF_F; l_i[i] = 0.f;
        #pragma unroll
        for (int j = 0; j < 4; j++) O[i][j] = 0.f;
    }

    for (int kt = 0; kt < SP / 64; kt++) {
        __syncthreads();   // prior PV reads of Vs/Pt complete before overwrite
        const float* kk = kb + (size_t)kt * 64 * HD;
        const float* vv = vb + (size_t)kt * 64 * HD;
        #pragma unroll
        for (int i = 0; i < 4; i++) {
            int idx = tid + i * 256;
            int r = idx >> 4, c4 = idx & 15;
            float4 v = *(const float4*)(kk + r * HD + c4 * 4);
            Kt[c4*4+0][r] = v.x; Kt[c4*4+1][r] = v.y;
            Kt[c4*4+2][r] = v.z; Kt[c4*4+3][r] = v.w;
            *(float4*)&Vs[r][c4*4] = *(const float4*)(vv + r * HD + c4 * 4);
        }
        __syncthreads();

        float s[4][4];
        #pragma unroll
        for (int i = 0; i < 4; i++)
            #pragma unroll
            for (int j = 0; j < 4; j++) s[i][j] = 0.f;

        #pragma unroll 8
        for (int d = 0; d < HD; d++) {
            float a[4], b[4];
            *(float4*)a = *(const float4*)&Qt[d][ty*4];
            *(float4*)b = *(const float4*)&Kt[d][tx*4];
            #pragma unroll
            for (int i = 0; i < 4; i++)
                #pragma unroll
                for (int j = 0; j < 4; j++)
                    s[i][j] = fmaf(a[i], b[j], s[i][j]);
        }

        // online softmax (rows owned by the 16-lane tx group)
        #pragma unroll
        for (int i = 0; i < 4; i++) {
            float rm = fmaxf(fmaxf(s[i][0], s[i][1]), fmaxf(s[i][2], s[i][3]));
            rm = fmaxf(rm, __shfl_xor_sync(0xffffffffu, rm, 1));
            rm = fmaxf(rm, __shfl_xor_sync(0xffffffffu, rm, 2));
            rm = fmaxf(rm, __shfl_xor_sync(0xffffffffu, rm, 4));
            rm = fmaxf(rm, __shfl_xor_sync(0xffffffffu, rm, 8));
            float mnew  = fmaxf(m_i[i], rm);
            float alpha = __expf(m_i[i] - mnew);
            float rs = 0.f;
            #pragma unroll
            for (int j = 0; j < 4; j++) {
                float p = __expf(s[i][j] - mnew);
                s[i][j] = p; rs += p;
            }
            rs += __shfl_xor_sync(0xffffffffu, rs, 1);
            rs += __shfl_xor_sync(0xffffffffu, rs, 2);
            rs += __shfl_xor_sync(0xffffffffu, rs, 4);
            rs += __shfl_xor_sync(0xffffffffu, rs, 8);
            l_i[i] = l_i[i] * alpha + rs;
            m_i[i] = mnew;
            #pragma unroll
            for (int j = 0; j < 4; j++) O[i][j] *= alpha;
        }

        #pragma unroll
        for (int i = 0; i < 4; i++)
            #pragma unroll
            for (int j = 0; j < 4; j++)
                Pt[tx*4+j][ty*4+i] = s[i][j];
        __syncthreads();

        #pragma unroll 8
        for (int k = 0; k < 64; k++) {
            float a[4], v4[4];
            *(float4*)a  = *(const float4*)&Pt[k][ty*4];
            *(float4*)v4 = *(const float4*)&Vs[k][tx*4];
            #pragma unroll
            for (int i = 0; i < 4; i++)
                #pragma unroll
                for (int j = 0; j < 4; j++)
                    O[i][j] = fmaf(a[i], v4[j], O[i][j]);
        }
    }

    #pragma unroll
    for (int i = 0; i < 4; i++) {
        float inv = 1.f / l_i[i];
        #pragma unroll
        for (int j = 0; j < 4; j++) O[i][j] *= inv;
    }

    // final maxpool over adjacent q rows; write in [B][H][SQ4][HD] layout,
    // which IS the reference's head-major reshape to [4096,1024].
    float4 r0, r1;
    r0.x = fmaxf(O[0][0], O[1][0]); r0.y = fmaxf(O[0][1], O[1][1]);
    r0.z = fmaxf(O[0][2], O[1][2]); r0.w = fmaxf(O[0][3], O[1][3]);
    r1.x = fmaxf(O[2][0], O[3][0]); r1.y = fmaxf(O[2][1], O[3][1]);
    r1.z = fmaxf(O[2][2], O[3][2]); r1.w = fmaxf(O[2][3], O[3][3]);
    size_t base = ((size_t)n * SQ4 + blockIdx.x * 32 + ty * 2) * HD + tx * 4;
    *(float4*)(g_A + base)      = r0;
    *(float4*)(g_A + base + HD) = r1;
}

// ---------------- kernel 4: output projection ------------------------------
__global__ __launch_bounds__(256, 2)
void out_gemm_kernel(const float* __restrict__ Wo, const float* __restrict__ bo,
                     float* __restrict__ out)
{
    gemm128(g_A, Wo, bo, out, EMBED, EMBED);
}

// ---------------- launch ---------------------------------------------------
extern "C" void kernel_launch(void* const* d_in, const int* in_sizes, int n_in,
                              void* d_out, int out_size)
{
    const float* x  = (const float*)d_in[0];
    const float* Wq = (const float*)d_in[1];
    const float* bq = (const float*)d_in[2];
    const float* Wk = (const float*)d_in[3];
    const float* bk = (const float*)d_in[4];
    const float* Wv = (const float*)d_in[5];
    const float* bv = (const float*)d_in[6];
    const float* Wo = (const float*)d_in[7];
    const float* bo = (const float*)d_in[8];
    float* out = (float*)d_out;

    const int smem_attn = 4 * 64 * LDT * sizeof(float);   // 69632 B
    cudaFuncSetAttribute(attn_kernel,
                         cudaFuncAttributeMaxDynamicSharedMemorySize, smem_attn);

    dim3 gQKV(EMBED / 128, M_QKV / 128, 3);          // 8 x 128 x 3
    qkv_gemm_kernel<<<gQKV, 256>>>(x, Wq, Wk, Wv, bq, bk, bv);

    pool_kernel<<<(3 * NPOOL * SP * (HD / 4)) / 256, 256>>>();   // 24576 blocks

    attn_kernel<<<dim3(SP / 64, NPOOL), 256, smem_attn>>>();     // 32 x 64

    out_gemm_kernel<<<dim3(EMBED / 128, (BATCH * SQ4) / 128), 256>>>(Wo, bo, out);
}

// round 5
// speedup vs baseline: 1.4326x; 1.4326x over previous
#include <cuda_runtime.h>
#include <cuda_bf16.h>
#include <math_constants.h>
#include <cstdint>

#define EMBED 1024
#define BATCH 4
#define SEQ 4096
#define NHEAD 16
#define HD 64
#define M_QKV (BATCH*SEQ)        /* 16384 */
#define NPOOL (BATCH*NHEAD)      /* 64 heads total */
#define SP (SEQ/2)               /* 2048 pooled kv/q length */
#define SQ4 (SEQ/4)              /* 1024 final pooled length */

// ---------------- scratch (device globals; no runtime allocation) ----------
__device__ float g_QKV[(size_t)3*M_QKV*EMBED];          // 192 MB
__device__ float g_q[(size_t)NPOOL*SP*HD];              // 32 MB
__device__ float g_k[(size_t)NPOOL*SP*HD];
__device__ float g_v[(size_t)NPOOL*SP*HD];
__device__ float g_A[(size_t)BATCH*SQ4*EMBED];          // 16 MB
__device__ __nv_bfloat16 g_xh[(size_t)M_QKV*EMBED];     // 32 MB
__device__ __nv_bfloat16 g_xl[(size_t)M_QKV*EMBED];
__device__ __nv_bfloat16 g_wth[(size_t)4*EMBED*EMBED];  // 8 MB (W^T: [n][k])
__device__ __nv_bfloat16 g_wtl[(size_t)4*EMBED*EMBED];
__device__ __nv_bfloat16 g_ah[(size_t)BATCH*SQ4*EMBED]; // 8 MB
__device__ __nv_bfloat16 g_al[(size_t)BATCH*SQ4*EMBED];

// ======================= PTX helpers ========================================
__device__ __forceinline__ uint32_t smem_u32(const void* p) {
    uint32_t a;
    asm("{ .reg .u64 t; cvta.to.shared.u64 t, %1; cvt.u32.u64 %0, t; }" : "=r"(a) : "l"(p));
    return a;
}
#define CP_ASYNC16(s, g) \
    asm volatile("cp.async.cg.shared.global [%0], [%1], 16;" :: "r"(s), "l"(g) : "memory")
#define CP_COMMIT() asm volatile("cp.async.commit_group;" ::: "memory")
#define CP_WAIT(n)  asm volatile("cp.async.wait_group %0;" :: "n"(n) : "memory")
#define LDMX4(d0, d1, d2, d3, a) \
    asm volatile("ldmatrix.sync.aligned.m8n8.x4.shared.b16 {%0,%1,%2,%3}, [%4];" \
                 : "=r"(d0), "=r"(d1), "=r"(d2), "=r"(d3) : "r"(a))

__device__ __forceinline__ void mma16816(float* c, const uint32_t* a, const uint32_t* b) {
    asm volatile(
        "mma.sync.aligned.m16n8k16.row.col.f32.bf16.bf16.f32 "
        "{%0,%1,%2,%3}, {%4,%5,%6,%7}, {%8,%9}, {%0,%1,%2,%3};"
        : "+f"(c[0]), "+f"(c[1]), "+f"(c[2]), "+f"(c[3])
        : "r"(a[0]), "r"(a[1]), "r"(a[2]), "r"(a[3]), "r"(b[0]), "r"(b[1]));
}

// ======================= HMMA split-bf16 GEMM ==============================
// C[M,1024] = A[M,1024] * W^T  (W^T stored [n][k]) + bias; split-bf16, fp32 acc.
// CTA tile 128x128, warp tile 64x32, K-chunk 32, cp.async double buffer.
#define KD 1024
#define STR 40                     /* smem row stride in bf16 elems (80 B) */
#define SA_H 0
#define SA_L 10240
#define SB_H 20480
#define SB_L 30720
#define BUFB 40960                 /* bytes per buffer */
#define SMEM_HM (2*BUFB)           /* 81920 */

__device__ __forceinline__ void hmma_load_tile(
    uint32_t sbuf, const __nv_bfloat16* Ah, const __nv_bfloat16* Al,
    const __nv_bfloat16* Bh, const __nv_bfloat16* Bl,
    int bm, int bn, int k0, int tid)
{
    #pragma unroll
    for (int i = 0; i < 2; i++) {
        int idx = tid + i * 256;           // 0..511
        int r = idx >> 2, c = idx & 3;     // row, 8-elem chunk
        uint32_t soff = (uint32_t)(r * STR + c * 8) * 2;
        size_t ga = (size_t)(bm + r) * KD + k0 + c * 8;
        size_t gb = (size_t)(bn + r) * KD + k0 + c * 8;
        CP_ASYNC16(sbuf + SA_H + soff, Ah + ga);
        CP_ASYNC16(sbuf + SA_L + soff, Al + ga);
        CP_ASYNC16(sbuf + SB_H + soff, Bh + gb);
        CP_ASYNC16(sbuf + SB_L + soff, Bl + gb);
    }
}

__device__ __forceinline__ void hmma_gemm_body(
    const __nv_bfloat16* __restrict__ Ah, const __nv_bfloat16* __restrict__ Al,
    const __nv_bfloat16* __restrict__ Bh, const __nv_bfloat16* __restrict__ Bl,
    const float* __restrict__ bias, float* __restrict__ C)
{
    extern __shared__ char smem[];
    const uint32_t sbase = smem_u32(smem);
    const int tid = threadIdx.x;
    const int lane = tid & 31, wid = tid >> 5;
    const int wm = wid & 1, wn = wid >> 1;      // warp grid 2 (m) x 4 (n)
    const int bm = blockIdx.y * 128;
    const int bn = blockIdx.x * 128;

    float acc[4][4][4];
    #pragma unroll
    for (int mt = 0; mt < 4; mt++)
        #pragma unroll
        for (int nt = 0; nt < 4; nt++)
            #pragma unroll
            for (int r = 0; r < 4; r++) acc[mt][nt][r] = 0.f;

    const int mat = lane >> 3, lr = lane & 7;
    const int a_roff = (mat & 1) * 8 + lr;      // A row within 16-tile
    const int a_coff = (mat >> 1) * 8;          // A col within k16
    const int b_roff = (mat >> 1) * 8 + lr;     // B (n) row within 16-group
    const int b_coff = (mat & 1) * 8;           // B col within k16

    hmma_load_tile(sbase, Ah, Al, Bh, Bl, bm, bn, 0, tid);
    CP_COMMIT();

    for (int kc = 0; kc < KD / 32; kc++) {
        const uint32_t sbuf = sbase + (uint32_t)(kc & 1) * BUFB;
        if (kc + 1 < KD / 32) {
            hmma_load_tile(sbase + (uint32_t)((kc + 1) & 1) * BUFB,
                           Ah, Al, Bh, Bl, bm, bn, (kc + 1) * 32, tid);
            CP_COMMIT();
            CP_WAIT(1);
        } else {
            CP_WAIT(0);
        }
        __syncthreads();

        #pragma unroll
        for (int kk = 0; kk < 32; kk += 16) {
            uint32_t ahi[4][4], alo[4][4];
            #pragma unroll
            for (int mt = 0; mt < 4; mt++) {
                uint32_t ad = sbuf + SA_H +
                    (uint32_t)((wm * 64 + mt * 16 + a_roff) * STR + kk + a_coff) * 2;
                LDMX4(ahi[mt][0], ahi[mt][1], ahi[mt][2], ahi[mt][3], ad);
                LDMX4(alo[mt][0], alo[mt][1], alo[mt][2], alo[mt][3], ad + (SA_L - SA_H));
            }
            uint32_t bhi[4][2], blo[4][2];
            #pragma unroll
            for (int g = 0; g < 2; g++) {
                uint32_t bd = sbuf + SB_H +
                    (uint32_t)((wn * 32 + g * 16 + b_roff) * STR + kk + b_coff) * 2;
                LDMX4(bhi[g*2][0], bhi[g*2][1], bhi[g*2+1][0], bhi[g*2+1][1], bd);
                LDMX4(blo[g*2][0], blo[g*2][1], blo[g*2+1][0], blo[g*2+1][1],
                      bd + (SB_L - SB_H));
            }
            #pragma unroll
            for (int mt = 0; mt < 4; mt++)
                #pragma unroll
                for (int nt = 0; nt < 4; nt++) {
                    mma16816(acc[mt][nt], ahi[mt], bhi[nt]);
                    mma16816(acc[mt][nt], ahi[mt], blo[nt]);
                    mma16816(acc[mt][nt], alo[mt], bhi[nt]);
                }
        }
        __syncthreads();
    }

    // epilogue: c0,c1 -> (row lane/4, col (lane%4)*2); c2,c3 -> row+8
    #pragma unroll
    for (int mt = 0; mt < 4; mt++) {
        #pragma unroll
        for (int nt = 0; nt < 4; nt++) {
            int row = bm + wm * 64 + mt * 16 + (lane >> 2);
            int col = bn + wn * 32 + nt * 8 + (lane & 3) * 2;
            float b0 = bias[col], b1 = bias[col + 1];
            float2 v0 = make_float2(acc[mt][nt][0] + b0, acc[mt][nt][1] + b1);
            float2 v1 = make_float2(acc[mt][nt][2] + b0, acc[mt][nt][3] + b1);
            *(float2*)(C + (size_t)row * EMBED + col) = v0;
            *(float2*)(C + (size_t)(row + 8) * EMBED + col) = v1;
        }
    }
}

__global__ __launch_bounds__(256, 1)
void qkv_hmma_kernel(const float* __restrict__ bq, const float* __restrict__ bk,
                     const float* __restrict__ bv)
{
    const int z = blockIdx.z;
    const float* bias = (z == 0) ? bq : (z == 1) ? bk : bv;
    hmma_gemm_body(g_xh, g_xl,
                   g_wth + (size_t)z * EMBED * EMBED, g_wtl + (size_t)z * EMBED * EMBED,
                   bias, g_QKV + (size_t)z * M_QKV * EMBED);
}

__global__ __launch_bounds__(256, 1)
void out_hmma_kernel(const float* __restrict__ bo, float* __restrict__ out)
{
    hmma_gemm_body(g_ah, g_al,
                   g_wth + (size_t)3 * EMBED * EMBED, g_wtl + (size_t)3 * EMBED * EMBED,
                   bo, out);
}

// ---------------- conversion kernels (globals referenced device-side!) -----
__global__ __launch_bounds__(256)
void conv_x_kernel(const float* __restrict__ s)
{
    int i = blockIdx.x * 256 + threadIdx.x;     // over float4 chunks
    float4 v = ((const float4*)s)[i];
    union { __nv_bfloat16 b[4]; uint2 u; } H, L;
    float f[4] = {v.x, v.y, v.z, v.w};
    #pragma unroll
    for (int j = 0; j < 4; j++) {
        H.b[j] = __float2bfloat16(f[j]);
        L.b[j] = __float2bfloat16(f[j] - __bfloat162float(H.b[j]));
    }
    ((uint2*)g_xh)[i] = H.u;
    ((uint2*)g_xl)[i] = L.u;
}

__global__ __launch_bounds__(256)
void conv_a_kernel()
{
    int i = blockIdx.x * 256 + threadIdx.x;     // over float4 chunks of g_A
    float4 v = ((const float4*)g_A)[i];
    union { __nv_bfloat16 b[4]; uint2 u; } H, L;
    float f[4] = {v.x, v.y, v.z, v.w};
    #pragma unroll
    for (int j = 0; j < 4; j++) {
        H.b[j] = __float2bfloat16(f[j]);
        L.b[j] = __float2bfloat16(f[j] - __bfloat162float(H.b[j]));
    }
    ((uint2*)g_ah)[i] = H.u;
    ((uint2*)g_al)[i] = L.u;
}

__global__ __launch_bounds__(256)
void conv_w_kernel(const float* __restrict__ Wq, const float* __restrict__ Wk,
                   const float* __restrict__ Wv, const float* __restrict__ Wo)
{
    __shared__ float t[32][33];
    const int z = blockIdx.z;
    const float* W = (z == 0) ? Wq : (z == 1) ? Wk : (z == 2) ? Wv : Wo;
    const int n0 = blockIdx.x * 32, k0 = blockIdx.y * 32;
    const int tx = threadIdx.x, ty = threadIdx.y;   // 32 x 8
    #pragma unroll
    for (int i = 0; i < 4; i++)
        t[ty + i*8][tx] = W[(size_t)(k0 + ty + i*8) * EMBED + n0 + tx];
    __syncthreads();
    #pragma unroll
    for (int i = 0; i < 4; i++) {
        int n = n0 + ty + i*8, k = k0 + tx;
        float v = t[tx][ty + i*8];
        __nv_bfloat16 hv = __float2bfloat16(v);
        size_t o = (size_t)z * EMBED * EMBED + (size_t)n * EMBED + k;
        g_wth[o] = hv;
        g_wtl[o] = __float2bfloat16(v - __bfloat162float(hv));
    }
}

// ---------------- head split + seq maxpool(2) -------------------------------
__global__ __launch_bounds__(256)
void pool_kernel()
{
    int idx = blockIdx.x * 256 + threadIdx.x;
    int c4 = idx & 15;
    int sp = (idx >> 4) & 2047;
    int n  = (idx >> 15) & 63;
    int z  = idx >> 21;
    int b = n >> 4, h = n & 15;
    const float* src = g_QKV + (size_t)z * M_QKV * EMBED
                     + (size_t)(b * SEQ + 2 * sp) * EMBED + h * HD + c4 * 4;
    float4 u = *(const float4*)src;
    float4 w = *(const float4*)(src + EMBED);
    float4 r;
    r.x = fmaxf(u.x, w.x); r.y = fmaxf(u.y, w.y);
    r.z = fmaxf(u.z, w.z); r.w = fmaxf(u.w, w.w);
    float* dstbase = (z == 0) ? g_q : (z == 1) ? g_k : g_v;
    *(float4*)(dstbase + ((size_t)n * SP + sp) * HD + c4 * 4) = r;
}

// ---------------- flash attention + final maxpool ---------------------------
#define LDT 68
__global__ __launch_bounds__(256)
void attn_kernel()
{
    extern __shared__ float sm[];
    float (*Qt)[LDT] = (float(*)[LDT])(sm);
    float (*Kt)[LDT] = (float(*)[LDT])(sm + 64*LDT);
    float (*Vs)[LDT] = (float(*)[LDT])(sm + 2*64*LDT);
    float (*Pt)[LDT] = (float(*)[LDT])(sm + 3*64*LDT);

    const int tid = threadIdx.x;
    const int tx = tid & 15, ty = tid >> 4;
    const int n  = blockIdx.y;
    const int q0 = blockIdx.x * 64;

    const float* qb = g_q + ((size_t)n * SP + q0) * HD;
    const float* kb = g_k + (size_t)n * SP * HD;
    const float* vb = g_v + (size_t)n * SP * HD;

    #pragma unroll
    for (int i = 0; i < 4; i++) {
        int idx = tid + i * 256;
        int r = idx >> 4, c4 = idx & 15;
        float4 v = *(const float4*)(qb + r * HD + c4 * 4);
        Qt[c4*4+0][r] = v.x * 0.125f; Qt[c4*4+1][r] = v.y * 0.125f;
        Qt[c4*4+2][r] = v.z * 0.125f; Qt[c4*4+3][r] = v.w * 0.125f;
    }

    float m_i[4], l_i[4], O[4][4];
    #pragma unroll
    for (int i = 0; i < 4; i++) {
        m_i[i] = -CUDART_INF_F; l_i[i] = 0.f;
        #pragma unroll
        for (int j = 0; j < 4; j++) O[i][j] = 0.f;
    }

    for (int kt = 0; kt < SP / 64; kt++) {
        __syncthreads();
        const float* kk = kb + (size_t)kt * 64 * HD;
        const float* vv = vb + (size_t)kt * 64 * HD;
        #pragma unroll
        for (int i = 0; i < 4; i++) {
            int idx = tid + i * 256;
            int r = idx >> 4, c4 = idx & 15;
            float4 v = *(const float4*)(kk + r * HD + c4 * 4);
            Kt[c4*4+0][r] = v.x; Kt[c4*4+1][r] = v.y;
            Kt[c4*4+2][r] = v.z; Kt[c4*4+3][r] = v.w;
            *(float4*)&Vs[r][c4*4] = *(const float4*)(vv + r * HD + c4 * 4);
        }
        __syncthreads();

        float s[4][4];
        #pragma unroll
        for (int i = 0; i < 4; i++)
            #pragma unroll
            for (int j = 0; j < 4; j++) s[i][j] = 0.f;

        #pragma unroll 8
        for (int d = 0; d < HD; d++) {
            float a[4], b[4];
            *(float4*)a = *(const float4*)&Qt[d][ty*4];
            *(float4*)b = *(const float4*)&Kt[d][tx*4];
            #pragma unroll
            for (int i = 0; i < 4; i++)
                #pragma unroll
                for (int j = 0; j < 4; j++)
                    s[i][j] = fmaf(a[i], b[j], s[i][j]);
        }

        #pragma unroll
        for (int i = 0; i < 4; i++) {
            float rm = fmaxf(fmaxf(s[i][0], s[i][1]), fmaxf(s[i][2], s[i][3]));
            rm = fmaxf(rm, __shfl_xor_sync(0xffffffffu, rm, 1));
            rm = fmaxf(rm, __shfl_xor_sync(0xffffffffu, rm, 2));
            rm = fmaxf(rm, __shfl_xor_sync(0xffffffffu, rm, 4));
            rm = fmaxf(rm, __shfl_xor_sync(0xffffffffu, rm, 8));
            float mnew  = fmaxf(m_i[i], rm);
            float alpha = __expf(m_i[i] - mnew);
            float rs = 0.f;
            #pragma unroll
            for (int j = 0; j < 4; j++) {
                float p = __expf(s[i][j] - mnew);
                s[i][j] = p; rs += p;
            }
            rs += __shfl_xor_sync(0xffffffffu, rs, 1);
            rs += __shfl_xor_sync(0xffffffffu, rs, 2);
            rs += __shfl_xor_sync(0xffffffffu, rs, 4);
            rs += __shfl_xor_sync(0xffffffffu, rs, 8);
            l_i[i] = l_i[i] * alpha + rs;
            m_i[i] = mnew;
            #pragma unroll
            for (int j = 0; j < 4; j++) O[i][j] *= alpha;
        }

        #pragma unroll
        for (int i = 0; i < 4; i++)
            #pragma unroll
            for (int j = 0; j < 4; j++)
                Pt[tx*4+j][ty*4+i] = s[i][j];
        __syncthreads();

        #pragma unroll 8
        for (int k = 0; k < 64; k++) {
            float a[4], v4[4];
            *(float4*)a  = *(const float4*)&Pt[k][ty*4];
            *(float4*)v4 = *(const float4*)&Vs[k][tx*4];
            #pragma unroll
            for (int i = 0; i < 4; i++)
                #pragma unroll
                for (int j = 0; j < 4; j++)
                    O[i][j] = fmaf(a[i], v4[j], O[i][j]);
        }
    }

    #pragma unroll
    for (int i = 0; i < 4; i++) {
        float inv = 1.f / l_i[i];
        #pragma unroll
        for (int j = 0; j < 4; j++) O[i][j] *= inv;
    }

    float4 r0, r1;
    r0.x = fmaxf(O[0][0], O[1][0]); r0.y = fmaxf(O[0][1], O[1][1]);
    r0.z = fmaxf(O[0][2], O[1][2]); r0.w = fmaxf(O[0][3], O[1][3]);
    r1.x = fmaxf(O[2][0], O[3][0]); r1.y = fmaxf(O[2][1], O[3][1]);
    r1.z = fmaxf(O[2][2], O[3][2]); r1.w = fmaxf(O[2][3], O[3][3]);
    size_t base = ((size_t)n * SQ4 + blockIdx.x * 32 + ty * 2) * HD + tx * 4;
    *(float4*)(g_A + base)      = r0;
    *(float4*)(g_A + base + HD) = r1;
}

// ---------------- launch ----------------------------------------------------
extern "C" void kernel_launch(void* const* d_in, const int* in_sizes, int n_in,
                              void* d_out, int out_size)
{
    const float* x  = (const float*)d_in[0];
    const float* Wq = (const float*)d_in[1];
    const float* bq = (const float*)d_in[2];
    const float* Wk = (const float*)d_in[3];
    const float* bk = (const float*)d_in[4];
    const float* Wv = (const float*)d_in[5];
    const float* bv = (const float*)d_in[6];
    const float* Wo = (const float*)d_in[7];
    const float* bo = (const float*)d_in[8];
    float* out = (float*)d_out;

    const int smem_attn = 4 * 64 * LDT * sizeof(float);
    cudaFuncSetAttribute(attn_kernel,
                         cudaFuncAttributeMaxDynamicSharedMemorySize, smem_attn);
    cudaFuncSetAttribute(qkv_hmma_kernel,
                         cudaFuncAttributeMaxDynamicSharedMemorySize, SMEM_HM);
    cudaFuncSetAttribute(out_hmma_kernel,
                         cudaFuncAttributeMaxDynamicSharedMemorySize, SMEM_HM);

    // 1. split-convert x; transpose+split weights (globals written device-side)
    conv_x_kernel<<<(M_QKV * EMBED / 4) / 256, 256>>>(x);
    conv_w_kernel<<<dim3(32, 32, 4), dim3(32, 8)>>>(Wq, Wk, Wv, Wo);

    // 2. QKV projection on tensor cores (HMMA split-bf16)
    qkv_hmma_kernel<<<dim3(EMBED / 128, M_QKV / 128, 3), 256, SMEM_HM>>>(bq, bk, bv);

    // 3. head split + pool
    pool_kernel<<<(3 * NPOOL * SP * (HD / 4)) / 256, 256>>>();

    // 4. attention + final pool
    attn_kernel<<<dim3(SP / 64, NPOOL), 256, smem_attn>>>();

    // 5. convert attn output; output projection on tensor cores
    conv_a_kernel<<<(BATCH * SQ4 * EMBED / 4) / 256, 256>>>();
    out_hmma_kernel<<<dim3(EMBED / 128, (BATCH * SQ4) / 128), 256, SMEM_HM>>>(bo, out);
}

// round 6
// speedup vs baseline: 2.7389x; 1.9119x over previous
#include <cuda_runtime.h>
#include <cuda_bf16.h>
#include <math_constants.h>
#include <cstdint>

#define EMBED 1024
#define BATCH 4
#define SEQ 4096
#define NHEAD 16
#define HD 64
#define M_QKV (BATCH*SEQ)        /* 16384 */
#define NPOOL (BATCH*NHEAD)      /* 64 heads total */
#define SP (SEQ/2)               /* 2048 pooled kv/q length */
#define SQ4 (SEQ/4)              /* 1024 final pooled length */

// ---------------- scratch (device globals; no runtime allocation) ----------
__device__ float g_QKV[(size_t)3*M_QKV*EMBED];          // 192 MB
__device__ float g_A[(size_t)BATCH*SQ4*EMBED];          // 16 MB
__device__ __nv_bfloat16 g_xh[(size_t)M_QKV*EMBED];     // 32 MB
__device__ __nv_bfloat16 g_xl[(size_t)M_QKV*EMBED];
__device__ __nv_bfloat16 g_wth[(size_t)4*EMBED*EMBED];  // 8 MB (W^T: [n][k])
__device__ __nv_bfloat16 g_wtl[(size_t)4*EMBED*EMBED];
__device__ __nv_bfloat16 g_ah[(size_t)BATCH*SQ4*EMBED]; // 8 MB
__device__ __nv_bfloat16 g_al[(size_t)BATCH*SQ4*EMBED];
// pooled q/k/v split-bf16, [head][sp][hd]
__device__ __nv_bfloat16 g_qh[(size_t)NPOOL*SP*HD];
__device__ __nv_bfloat16 g_ql[(size_t)NPOOL*SP*HD];
__device__ __nv_bfloat16 g_kh[(size_t)NPOOL*SP*HD];
__device__ __nv_bfloat16 g_kl[(size_t)NPOOL*SP*HD];
__device__ __nv_bfloat16 g_vh[(size_t)NPOOL*SP*HD];
__device__ __nv_bfloat16 g_vl[(size_t)NPOOL*SP*HD];

// ======================= PTX helpers ========================================
__device__ __forceinline__ uint32_t smem_u32(const void* p) {
    uint32_t a;
    asm("{ .reg .u64 t; cvta.to.shared.u64 t, %1; cvt.u32.u64 %0, t; }" : "=r"(a) : "l"(p));
    return a;
}
#define CP_ASYNC16(s, g) \
    asm volatile("cp.async.cg.shared.global [%0], [%1], 16;" :: "r"(s), "l"(g) : "memory")
#define CP_COMMIT() asm volatile("cp.async.commit_group;" ::: "memory")
#define CP_WAIT(n)  asm volatile("cp.async.wait_group %0;" :: "n"(n) : "memory")
#define LDMX4(d0, d1, d2, d3, a) \
    asm volatile("ldmatrix.sync.aligned.m8n8.x4.shared.b16 {%0,%1,%2,%3}, [%4];" \
                 : "=r"(d0), "=r"(d1), "=r"(d2), "=r"(d3) : "r"(a))
#define LDMX4T(d0, d1, d2, d3, a) \
    asm volatile("ldmatrix.sync.aligned.m8n8.x4.trans.shared.b16 {%0,%1,%2,%3}, [%4];" \
                 : "=r"(d0), "=r"(d1), "=r"(d2), "=r"(d3) : "r"(a))

__device__ __forceinline__ void mma16816(float* c, const uint32_t* a, const uint32_t* b) {
    asm volatile(
        "mma.sync.aligned.m16n8k16.row.col.f32.bf16.bf16.f32 "
        "{%0,%1,%2,%3}, {%4,%5,%6,%7}, {%8,%9}, {%0,%1,%2,%3};"
        : "+f"(c[0]), "+f"(c[1]), "+f"(c[2]), "+f"(c[3])
        : "r"(a[0]), "r"(a[1]), "r"(a[2]), "r"(a[3]), "r"(b[0]), "r"(b[1]));
}

// pack two fp32 into bf16x2 hi part + bf16x2 lo residual (exact split)
__device__ __forceinline__ void pack_split(float s0, float s1, uint32_t& h, uint32_t& l) {
    uint32_t hp;
    asm("cvt.rn.bf16x2.f32 %0, %1, %2;" : "=r"(hp) : "f"(s1), "f"(s0));
    float h0 = __uint_as_float(hp << 16);
    float h1 = __uint_as_float(hp & 0xffff0000u);
    float l0 = s0 - h0, l1 = s1 - h1;
    h = hp;
    asm("cvt.rn.bf16x2.f32 %0, %1, %2;" : "=r"(l) : "f"(l1), "f"(l0));
}

// ======================= HMMA split-bf16 GEMM ==============================
#define KD 1024
#define STR 40                     /* smem row stride in bf16 elems (80 B) */
#define SA_H 0
#define SA_L 10240
#define SB_H 20480
#define SB_L 30720
#define BUFB 40960
#define SMEM_HM (2*BUFB)           /* 81920 */

__device__ __forceinline__ void hmma_load_tile(
    uint32_t sbuf, const __nv_bfloat16* Ah, const __nv_bfloat16* Al,
    const __nv_bfloat16* Bh, const __nv_bfloat16* Bl,
    int bm, int bn, int k0, int tid)
{
    #pragma unroll
    for (int i = 0; i < 2; i++) {
        int idx = tid + i * 256;
        int r = idx >> 2, c = idx & 3;
        uint32_t soff = (uint32_t)(r * STR + c * 8) * 2;
        size_t ga = (size_t)(bm + r) * KD + k0 + c * 8;
        size_t gb = (size_t)(bn + r) * KD + k0 + c * 8;
        CP_ASYNC16(sbuf + SA_H + soff, Ah + ga);
        CP_ASYNC16(sbuf + SA_L + soff, Al + ga);
        CP_ASYNC16(sbuf + SB_H + soff, Bh + gb);
        CP_ASYNC16(sbuf + SB_L + soff, Bl + gb);
    }
}

__device__ __forceinline__ void hmma_gemm_body(
    const __nv_bfloat16* __restrict__ Ah, const __nv_bfloat16* __restrict__ Al,
    const __nv_bfloat16* __restrict__ Bh, const __nv_bfloat16* __restrict__ Bl,
    const float* __restrict__ bias, float* __restrict__ C)
{
    extern __shared__ char smem[];
    const uint32_t sbase = smem_u32(smem);
    const int tid = threadIdx.x;
    const int lane = tid & 31, wid = tid >> 5;
    const int wm = wid & 1, wn = wid >> 1;
    const int bm = blockIdx.y * 128;
    const int bn = blockIdx.x * 128;

    float acc[4][4][4];
    #pragma unroll
    for (int mt = 0; mt < 4; mt++)
        #pragma unroll
        for (int nt = 0; nt < 4; nt++)
            #pragma unroll
            for (int r = 0; r < 4; r++) acc[mt][nt][r] = 0.f;

    const int mat = lane >> 3, lr = lane & 7;
    const int a_roff = (mat & 1) * 8 + lr;
    const int a_coff = (mat >> 1) * 8;
    const int b_roff = (mat >> 1) * 8 + lr;
    const int b_coff = (mat & 1) * 8;

    hmma_load_tile(sbase, Ah, Al, Bh, Bl, bm, bn, 0, tid);
    CP_COMMIT();

    for (int kc = 0; kc < KD / 32; kc++) {
        const uint32_t sbuf = sbase + (uint32_t)(kc & 1) * BUFB;
        if (kc + 1 < KD / 32) {
            hmma_load_tile(sbase + (uint32_t)((kc + 1) & 1) * BUFB,
                           Ah, Al, Bh, Bl, bm, bn, (kc + 1) * 32, tid);
            CP_COMMIT();
            CP_WAIT(1);
        } else {
            CP_WAIT(0);
        }
        __syncthreads();

        #pragma unroll
        for (int kk = 0; kk < 32; kk += 16) {
            uint32_t ahi[4][4], alo[4][4];
            #pragma unroll
            for (int mt = 0; mt < 4; mt++) {
                uint32_t ad = sbuf + SA_H +
                    (uint32_t)((wm * 64 + mt * 16 + a_roff) * STR + kk + a_coff) * 2;
                LDMX4(ahi[mt][0], ahi[mt][1], ahi[mt][2], ahi[mt][3], ad);
                LDMX4(alo[mt][0], alo[mt][1], alo[mt][2], alo[mt][3], ad + (SA_L - SA_H));
            }
            uint32_t bhi[4][2], blo[4][2];
            #pragma unroll
            for (int g = 0; g < 2; g++) {
                uint32_t bd = sbuf + SB_H +
                    (uint32_t)((wn * 32 + g * 16 + b_roff) * STR + kk + b_coff) * 2;
                LDMX4(bhi[g*2][0], bhi[g*2][1], bhi[g*2+1][0], bhi[g*2+1][1], bd);
                LDMX4(blo[g*2][0], blo[g*2][1], blo[g*2+1][0], blo[g*2+1][1],
                      bd + (SB_L - SB_H));
            }
            #pragma unroll
            for (int mt = 0; mt < 4; mt++)
                #pragma unroll
                for (int nt = 0; nt < 4; nt++) {
                    mma16816(acc[mt][nt], ahi[mt], bhi[nt]);
                    mma16816(acc[mt][nt], ahi[mt], blo[nt]);
                    mma16816(acc[mt][nt], alo[mt], bhi[nt]);
                }
        }
        __syncthreads();
    }

    #pragma unroll
    for (int mt = 0; mt < 4; mt++) {
        #pragma unroll
        for (int nt = 0; nt < 4; nt++) {
            int row = bm + wm * 64 + mt * 16 + (lane >> 2);
            int col = bn + wn * 32 + nt * 8 + (lane & 3) * 2;
            float b0 = bias[col], b1 = bias[col + 1];
            float2 v0 = make_float2(acc[mt][nt][0] + b0, acc[mt][nt][1] + b1);
            float2 v1 = make_float2(acc[mt][nt][2] + b0, acc[mt][nt][3] + b1);
            *(float2*)(C + (size_t)row * EMBED + col) = v0;
            *(float2*)(C + (size_t)(row + 8) * EMBED + col) = v1;
        }
    }
}

__global__ __launch_bounds__(256, 1)
void qkv_hmma_kernel(const float* __restrict__ bq, const float* __restrict__ bk,
                     const float* __restrict__ bv)
{
    const int z = blockIdx.z;
    const float* bias = (z == 0) ? bq : (z == 1) ? bk : bv;
    hmma_gemm_body(g_xh, g_xl,
                   g_wth + (size_t)z * EMBED * EMBED, g_wtl + (size_t)z * EMBED * EMBED,
                   bias, g_QKV + (size_t)z * M_QKV * EMBED);
}

__global__ __launch_bounds__(256, 1)
void out_hmma_kernel(const float* __restrict__ bo, float* __restrict__ out)
{
    hmma_gemm_body(g_ah, g_al,
                   g_wth + (size_t)3 * EMBED * EMBED, g_wtl + (size_t)3 * EMBED * EMBED,
                   bo, out);
}

// ---------------- conversion kernels ---------------------------------------
__global__ __launch_bounds__(256)
void conv_x_kernel(const float* __restrict__ s)
{
    int i = blockIdx.x * 256 + threadIdx.x;
    float4 v = ((const float4*)s)[i];
    union { __nv_bfloat16 b[4]; uint2 u; } H, L;
    float f[4] = {v.x, v.y, v.z, v.w};
    #pragma unroll
    for (int j = 0; j < 4; j++) {
        H.b[j] = __float2bfloat16(f[j]);
        L.b[j] = __float2bfloat16(f[j] - __bfloat162float(H.b[j]));
    }
    ((uint2*)g_xh)[i] = H.u;
    ((uint2*)g_xl)[i] = L.u;
}

__global__ __launch_bounds__(256)
void conv_a_kernel()
{
    int i = blockIdx.x * 256 + threadIdx.x;
    float4 v = ((const float4*)g_A)[i];
    union { __nv_bfloat16 b[4]; uint2 u; } H, L;
    float f[4] = {v.x, v.y, v.z, v.w};
    #pragma unroll
    for (int j = 0; j < 4; j++) {
        H.b[j] = __float2bfloat16(f[j]);
        L.b[j] = __float2bfloat16(f[j] - __bfloat162float(H.b[j]));
    }
    ((uint2*)g_ah)[i] = H.u;
    ((uint2*)g_al)[i] = L.u;
}

__global__ __launch_bounds__(256)
void conv_w_kernel(const float* __restrict__ Wq, const float* __restrict__ Wk,
                   const float* __restrict__ Wv, const float* __restrict__ Wo)
{
    __shared__ float t[32][33];
    const int z = blockIdx.z;
    const float* W = (z == 0) ? Wq : (z == 1) ? Wk : (z == 2) ? Wv : Wo;
    const int n0 = blockIdx.x * 32, k0 = blockIdx.y * 32;
    const int tx = threadIdx.x, ty = threadIdx.y;
    #pragma unroll
    for (int i = 0; i < 4; i++)
        t[ty + i*8][tx] = W[(size_t)(k0 + ty + i*8) * EMBED + n0 + tx];
    __syncthreads();
    #pragma unroll
    for (int i = 0; i < 4; i++) {
        int n = n0 + ty + i*8, k = k0 + tx;
        float v = t[tx][ty + i*8];
        __nv_bfloat16 hv = __float2bfloat16(v);
        size_t o = (size_t)z * EMBED * EMBED + (size_t)n * EMBED + k;
        g_wth[o] = hv;
        g_wtl[o] = __float2bfloat16(v - __bfloat162float(hv));
    }
}

// ---------------- head split + seq maxpool(2) + bf16 split ------------------
__global__ __launch_bounds__(256)
void pool_kernel()
{
    int idx = blockIdx.x * 256 + threadIdx.x;
    int c4 = idx & 15;
    int sp = (idx >> 4) & 2047;
    int n  = (idx >> 15) & 63;
    int z  = idx >> 21;
    int b = n >> 4, h = n & 15;
    const float* src = g_QKV + (size_t)z * M_QKV * EMBED
                     + (size_t)(b * SEQ + 2 * sp) * EMBED + h * HD + c4 * 4;
    float4 u = *(const float4*)src;
    float4 w = *(const float4*)(src + EMBED);
    float f[4];
    f[0] = fmaxf(u.x, w.x); f[1] = fmaxf(u.y, w.y);
    f[2] = fmaxf(u.z, w.z); f[3] = fmaxf(u.w, w.w);
    if (z == 0) {  // q gets the 1/sqrt(hd) scale (exact power of two)
        #pragma unroll
        for (int j = 0; j < 4; j++) f[j] *= 0.125f;
    }
    union { __nv_bfloat16 b[4]; uint2 u; } H, L;
    #pragma unroll
    for (int j = 0; j < 4; j++) {
        H.b[j] = __float2bfloat16(f[j]);
        L.b[j] = __float2bfloat16(f[j] - __bfloat162float(H.b[j]));
    }
    __nv_bfloat16* dh = (z == 0) ? g_qh : (z == 1) ? g_kh : g_vh;
    __nv_bfloat16* dl = (z == 0) ? g_ql : (z == 1) ? g_kl : g_vl;
    size_t o = ((size_t)n * SP + sp) * HD + c4 * 4;
    *(uint2*)(dh + o) = H.u;
    *(uint2*)(dl + o) = L.u;
}

// ---------------- HMMA flash attention + final maxpool ----------------------
#define ASTR 72                     /* padded smem stride (elems): 9 x 16B */
#define QLOFF 18432                 /* 128*72*2 */
#define KVOFF 36864
#define TILEB 9216                  /* 64*72*2 */
#define KVBUF 36864                 /* 4 tiles */
#define SMEM_AT (KVOFF + 2*KVBUF)   /* 110592 */

__device__ __forceinline__ void attn_load_kv(uint32_t sbase, int n, int kt,
                                             int buf, int tid)
{
    uint32_t base = sbase + KVOFF + (uint32_t)buf * KVBUF;
    #pragma unroll
    for (int i = 0; i < 8; i++) {
        int idx = tid + i * 256;
        int arr = idx >> 9, r = (idx >> 3) & 63, c = idx & 7;
        const __nv_bfloat16* sb = (arr == 0) ? g_kh : (arr == 1) ? g_kl
                                 : (arr == 2) ? g_vh : g_vl;
        const __nv_bfloat16* src = sb + ((size_t)n * SP + kt * 64 + r) * HD + c * 8;
        CP_ASYNC16(base + (uint32_t)arr * TILEB + (uint32_t)(r * ASTR + c * 8) * 2, src);
    }
}

__global__ __launch_bounds__(256)
void attn_kernel()
{
    extern __shared__ char smem[];
    const uint32_t sbase = smem_u32(smem);
    const int tid = threadIdx.x, lane = tid & 31, w = tid >> 5;
    const int n = blockIdx.y, Q0 = blockIdx.x * 128;
    const int lr = lane & 7, mat = lane >> 3;
    const int a_roff = (mat & 1) * 8 + lr, a_coff = (mat >> 1) * 8;
    const int b_roff = (mat >> 1) * 8 + lr, b_coff = (mat & 1) * 8;
    const int v_roff = (mat & 1) * 8 + lr, v_coff = (mat >> 1) * 8;

    // load Q tile (hi+lo): 2048 16B chunks
    #pragma unroll
    for (int i = 0; i < 8; i++) {
        int idx = tid + i * 256;
        int arr = idx >> 10, r = (idx >> 3) & 127, c = idx & 7;
        const __nv_bfloat16* src = (arr ? g_ql : g_qh)
                                 + ((size_t)n * SP + Q0 + r) * HD + c * 8;
        CP_ASYNC16(sbase + (uint32_t)arr * QLOFF + (uint32_t)(r * ASTR + c * 8) * 2, src);
    }
    attn_load_kv(sbase, n, 0, 0, tid);
    CP_COMMIT();

    float Sv[8][4], O[8][4];
    float m1 = -CUDART_INF_F, m2 = -CUDART_INF_F, l1 = 0.f, l2 = 0.f;
    #pragma unroll
    for (int t = 0; t < 8; t++)
        #pragma unroll
        for (int r = 0; r < 4; r++) O[t][r] = 0.f;

    for (int kt = 0; kt < SP / 64; kt++) {
        if (kt + 1 < SP / 64) {
            attn_load_kv(sbase, n, kt + 1, (kt + 1) & 1, tid);
            CP_COMMIT();
            CP_WAIT(1);
        } else {
            CP_WAIT(0);
        }
        __syncthreads();
        const uint32_t kb = sbase + KVOFF + (uint32_t)(kt & 1) * KVBUF;

        // ---- S = Q K^T (split-bf16, 3 terms) ----
        #pragma unroll
        for (int t = 0; t < 8; t++)
            #pragma unroll
            for (int r = 0; r < 4; r++) Sv[t][r] = 0.f;

        #pragma unroll
        for (int k4 = 0; k4 < 4; k4++) {
            uint32_t aqh[4], aql[4];
            uint32_t qa = sbase + (uint32_t)((w * 16 + a_roff) * ASTR + k4 * 16 + a_coff) * 2;
            LDMX4(aqh[0], aqh[1], aqh[2], aqh[3], qa);
            LDMX4(aql[0], aql[1], aql[2], aql[3], qa + QLOFF);
            uint32_t khf[8][2], klf[8][2];
            #pragma unroll
            for (int g = 0; g < 4; g++) {
                uint32_t ka = kb + (uint32_t)((g * 16 + b_roff) * ASTR + k4 * 16 + b_coff) * 2;
                LDMX4(khf[2*g][0], khf[2*g][1], khf[2*g+1][0], khf[2*g+1][1], ka);
                LDMX4(klf[2*g][0], klf[2*g][1], klf[2*g+1][0], klf[2*g+1][1], ka + TILEB);
            }
            #pragma unroll
            for (int t = 0; t < 8; t++) {
                mma16816(Sv[t], aqh, khf[t]);
                mma16816(Sv[t], aqh, klf[t]);
                mma16816(Sv[t], aql, khf[t]);
            }
        }

        // ---- online softmax (rows r1=lane/4, r2=r1+8) ----
        float mx1 = -CUDART_INF_F, mx2 = -CUDART_INF_F;
        #pragma unroll
        for (int t = 0; t < 8; t++) {
            mx1 = fmaxf(mx1, fmaxf(Sv[t][0], Sv[t][1]));
            mx2 = fmaxf(mx2, fmaxf(Sv[t][2], Sv[t][3]));
        }
        mx1 = fmaxf(mx1, __shfl_xor_sync(0xffffffffu, mx1, 1));
        mx1 = fmaxf(mx1, __shfl_xor_sync(0xffffffffu, mx1, 2));
        mx2 = fmaxf(mx2, __shfl_xor_sync(0xffffffffu, mx2, 1));
        mx2 = fmaxf(mx2, __shfl_xor_sync(0xffffffffu, mx2, 2));
        float mn1 = fmaxf(m1, mx1), mn2 = fmaxf(m2, mx2);
        float al1 = __expf(m1 - mn1), al2 = __expf(m2 - mn2);
        m1 = mn1; m2 = mn2;
        float rs1 = 0.f, rs2 = 0.f;
        #pragma unroll
        for (int t = 0; t < 8; t++) {
            Sv[t][0] = __expf(Sv[t][0] - mn1);
            Sv[t][1] = __expf(Sv[t][1] - mn1);
            Sv[t][2] = __expf(Sv[t][2] - mn2);
            Sv[t][3] = __expf(Sv[t][3] - mn2);
            rs1 += Sv[t][0] + Sv[t][1];
            rs2 += Sv[t][2] + Sv[t][3];
        }
        rs1 += __shfl_xor_sync(0xffffffffu, rs1, 1);
        rs1 += __shfl_xor_sync(0xffffffffu, rs1, 2);
        rs2 += __shfl_xor_sync(0xffffffffu, rs2, 1);
        rs2 += __shfl_xor_sync(0xffffffffu, rs2, 2);
        l1 = l1 * al1 + rs1;
        l2 = l2 * al2 + rs2;
        #pragma unroll
        for (int t = 0; t < 8; t++) {
            O[t][0] *= al1; O[t][1] *= al1;
            O[t][2] *= al2; O[t][3] *= al2;
        }

        // ---- O += P V (split-bf16, 3 terms; P built in registers) ----
        #pragma unroll
        for (int jj = 0; jj < 4; jj++) {
            uint32_t ph[4], pl[4];
            pack_split(Sv[2*jj][0],   Sv[2*jj][1],   ph[0], pl[0]);
            pack_split(Sv[2*jj][2],   Sv[2*jj][3],   ph[1], pl[1]);
            pack_split(Sv[2*jj+1][0], Sv[2*jj+1][1], ph[2], pl[2]);
            pack_split(Sv[2*jj+1][2], Sv[2*jj+1][3], ph[3], pl[3]);
            uint32_t vhf[8][2], vlf[8][2];
            #pragma unroll
            for (int g = 0; g < 4; g++) {
                uint32_t va = kb + 2 * TILEB +
                    (uint32_t)((jj * 16 + v_roff) * ASTR + g * 16 + v_coff) * 2;
                LDMX4T(vhf[2*g][0], vhf[2*g][1], vhf[2*g+1][0], vhf[2*g+1][1], va);
                LDMX4T(vlf[2*g][0], vlf[2*g][1], vlf[2*g+1][0], vlf[2*g+1][1], va + TILEB);
            }
            #pragma unroll
            for (int t = 0; t < 8; t++) {
                mma16816(O[t], ph, vhf[t]);
                mma16816(O[t], ph, vlf[t]);
                mma16816(O[t], pl, vhf[t]);
            }
        }
        __syncthreads();
    }

    // ---- epilogue: /l, q-pair maxpool via shfl, write head-major g_A ----
    const float inv1 = 1.f / l1, inv2 = 1.f / l2;
    const int prow1 = Q0 / 2 + w * 8 + (lane >> 3);        // valid for even group
    const int prow2 = prow1 + 4;
    #pragma unroll
    for (int t = 0; t < 8; t++) {
        float o0 = O[t][0] * inv1, o1 = O[t][1] * inv1;
        float o2 = O[t][2] * inv2, o3 = O[t][3] * inv2;
        float p0 = __shfl_xor_sync(0xffffffffu, o0, 4);
        float p1 = __shfl_xor_sync(0xffffffffu, o1, 4);
        float p2 = __shfl_xor_sync(0xffffffffu, o2, 4);
        float p3 = __shfl_xor_sync(0xffffffffu, o3, 4);
        if ((lane & 4) == 0) {
            int col = t * 8 + (lane & 3) * 2;
            float2 w0 = make_float2(fmaxf(o0, p0), fmaxf(o1, p1));
            float2 w1 = make_float2(fmaxf(o2, p2), fmaxf(o3, p3));
            *(float2*)(g_A + ((size_t)n * SQ4 + prow1) * HD + col) = w0;
            *(float2*)(g_A + ((size_t)n * SQ4 + prow2) * HD + col) = w1;
        }
    }
}

// ---------------- launch ----------------------------------------------------
extern "C" void kernel_launch(void* const* d_in, const int* in_sizes, int n_in,
                              void* d_out, int out_size)
{
    const float* x  = (const float*)d_in[0];
    const float* Wq = (const float*)d_in[1];
    const float* bq = (const float*)d_in[2];
    const float* Wk = (const float*)d_in[3];
    const float* bk = (const float*)d_in[4];
    const float* Wv = (const float*)d_in[5];
    const float* bv = (const float*)d_in[6];
    const float* Wo = (const float*)d_in[7];
    const float* bo = (const float*)d_in[8];
    float* out = (float*)d_out;

    cudaFuncSetAttribute(attn_kernel,
                         cudaFuncAttributeMaxDynamicSharedMemorySize, SMEM_AT);
    cudaFuncSetAttribute(qkv_hmma_kernel,
                         cudaFuncAttributeMaxDynamicSharedMemorySize, SMEM_HM);
    cudaFuncSetAttribute(out_hmma_kernel,
                         cudaFuncAttributeMaxDynamicSharedMemorySize, SMEM_HM);

    // 1. split-convert x; transpose+split weights
    conv_x_kernel<<<(M_QKV * EMBED / 4) / 256, 256>>>(x);
    conv_w_kernel<<<dim3(32, 32, 4), dim3(32, 8)>>>(Wq, Wk, Wv, Wo);

    // 2. QKV projection on tensor cores
    qkv_hmma_kernel<<<dim3(EMBED / 128, M_QKV / 128, 3), 256, SMEM_HM>>>(bq, bk, bv);

    // 3. head split + pool + bf16 split
    pool_kernel<<<(3 * NPOOL * SP * (HD / 4)) / 256, 256>>>();

    // 4. HMMA flash attention + final pool
    attn_kernel<<<dim3(SP / 128, NPOOL), 256, SMEM_AT>>>();

    // 5. convert attn output; output projection on tensor cores
    conv_a_kernel<<<(BATCH * SQ4 * EMBED / 4) / 256, 256>>>();
    out_hmma_kernel<<<dim3(EMBED / 128, (BATCH * SQ4) / 128), 256, SMEM_HM>>>(bo, out);
}

// round 7
// speedup vs baseline: 2.7396x; 1.0003x over previous
#include <cuda_runtime.h>
#include <cuda_bf16.h>
#include <math_constants.h>
#include <cstdint>

#define EMBED 1024
#define BATCH 4
#define SEQ 4096
#define NHEAD 16
#define HD 64
#define M_QKV (BATCH*SEQ)        /* 16384 */
#define NPOOL (BATCH*NHEAD)      /* 64 heads total */
#define SP (SEQ/2)               /* 2048 pooled kv/q length */
#define SQ4 (SEQ/4)              /* 1024 final pooled length */

// ---------------- scratch (device globals; no runtime allocation) ----------
__device__ float g_QKV[(size_t)3*M_QKV*EMBED];          // 192 MB
__device__ float g_A[(size_t)BATCH*SQ4*EMBED];          // 16 MB
__device__ __nv_bfloat16 g_xh[(size_t)M_QKV*EMBED];     // 32 MB
__device__ __nv_bfloat16 g_xl[(size_t)M_QKV*EMBED];
__device__ __nv_bfloat16 g_wth[(size_t)4*EMBED*EMBED];  // 8 MB (W^T: [n][k])
__device__ __nv_bfloat16 g_wtl[(size_t)4*EMBED*EMBED];
__device__ __nv_bfloat16 g_ah[(size_t)BATCH*SQ4*EMBED]; // 8 MB
__device__ __nv_bfloat16 g_al[(size_t)BATCH*SQ4*EMBED];
// pooled q/k/v split-bf16, [head][sp][hd]
__device__ __nv_bfloat16 g_qh[(size_t)NPOOL*SP*HD];
__device__ __nv_bfloat16 g_ql[(size_t)NPOOL*SP*HD];
__device__ __nv_bfloat16 g_kh[(size_t)NPOOL*SP*HD];
__device__ __nv_bfloat16 g_kl[(size_t)NPOOL*SP*HD];
__device__ __nv_bfloat16 g_vh[(size_t)NPOOL*SP*HD];
__device__ __nv_bfloat16 g_vl[(size_t)NPOOL*SP*HD];

// ======================= PTX helpers ========================================
__device__ __forceinline__ uint32_t smem_u32(const void* p) {
    uint32_t a;
    asm("{ .reg .u64 t; cvta.to.shared.u64 t, %1; cvt.u32.u64 %0, t; }" : "=r"(a) : "l"(p));
    return a;
}
#define CP_ASYNC16(s, g) \
    asm volatile("cp.async.cg.shared.global [%0], [%1], 16;" :: "r"(s), "l"(g) : "memory")
#define CP_COMMIT() asm volatile("cp.async.commit_group;" ::: "memory")
#define CP_WAIT(n)  asm volatile("cp.async.wait_group %0;" :: "n"(n) : "memory")
#define LDMX4(d0, d1, d2, d3, a) \
    asm volatile("ldmatrix.sync.aligned.m8n8.x4.shared.b16 {%0,%1,%2,%3}, [%4];" \
                 : "=r"(d0), "=r"(d1), "=r"(d2), "=r"(d3) : "r"(a))
#define LDMX4T(d0, d1, d2, d3, a) \
    asm volatile("ldmatrix.sync.aligned.m8n8.x4.trans.shared.b16 {%0,%1,%2,%3}, [%4];" \
                 : "=r"(d0), "=r"(d1), "=r"(d2), "=r"(d3) : "r"(a))

__device__ __forceinline__ void mma16816(float* c, const uint32_t* a, const uint32_t* b) {
    asm volatile(
        "mma.sync.aligned.m16n8k16.row.col.f32.bf16.bf16.f32 "
        "{%0,%1,%2,%3}, {%4,%5,%6,%7}, {%8,%9}, {%0,%1,%2,%3};"
        : "+f"(c[0]), "+f"(c[1]), "+f"(c[2]), "+f"(c[3])
        : "r"(a[0]), "r"(a[1]), "r"(a[2]), "r"(a[3]), "r"(b[0]), "r"(b[1]));
}

// pack two fp32 into bf16x2 hi part + bf16x2 lo residual (exact split)
__device__ __forceinline__ void pack_split(float s0, float s1, uint32_t& h, uint32_t& l) {
    uint32_t hp;
    asm("cvt.rn.bf16x2.f32 %0, %1, %2;" : "=r"(hp) : "f"(s1), "f"(s0));
    float h0 = __uint_as_float(hp << 16);
    float h1 = __uint_as_float(hp & 0xffff0000u);
    float l0 = s0 - h0, l1 = s1 - h1;
    h = hp;
    asm("cvt.rn.bf16x2.f32 %0, %1, %2;" : "=r"(l) : "f"(l1), "f"(l0));
}

// ======================= HMMA split-bf16 GEMM ==============================
#define KD 1024
#define STR 40                     /* smem row stride in bf16 elems (80 B) */
#define SA_H 0
#define SA_L 10240
#define SB_H 20480
#define SB_L 30720
#define BUFB 40960
#define SMEM_HM (2*BUFB)           /* 81920 */

__device__ __forceinline__ void hmma_load_tile(
    uint32_t sbuf, const __nv_bfloat16* Ah, const __nv_bfloat16* Al,
    const __nv_bfloat16* Bh, const __nv_bfloat16* Bl,
    int bm, int bn, int k0, int tid)
{
    #pragma unroll
    for (int i = 0; i < 2; i++) {
        int idx = tid + i * 256;
        int r = idx >> 2, c = idx & 3;
        uint32_t soff = (uint32_t)(r * STR + c * 8) * 2;
        size_t ga = (size_t)(bm + r) * KD + k0 + c * 8;
        size_t gb = (size_t)(bn + r) * KD + k0 + c * 8;
        CP_ASYNC16(sbuf + SA_H + soff, Ah + ga);
        CP_ASYNC16(sbuf + SA_L + soff, Al + ga);
        CP_ASYNC16(sbuf + SB_H + soff, Bh + gb);
        CP_ASYNC16(sbuf + SB_L + soff, Bl + gb);
    }
}

__device__ __forceinline__ void hmma_gemm_body(
    const __nv_bfloat16* __restrict__ Ah, const __nv_bfloat16* __restrict__ Al,
    const __nv_bfloat16* __restrict__ Bh, const __nv_bfloat16* __restrict__ Bl,
    const float* __restrict__ bias, float* __restrict__ C)
{
    extern __shared__ char smem[];
    const uint32_t sbase = smem_u32(smem);
    const int tid = threadIdx.x;
    const int lane = tid & 31, wid = tid >> 5;
    const int wm = wid & 1, wn = wid >> 1;
    const int bm = blockIdx.y * 128;
    const int bn = blockIdx.x * 128;

    float acc[4][4][4];
    #pragma unroll
    for (int mt = 0; mt < 4; mt++)
        #pragma unroll
        for (int nt = 0; nt < 4; nt++)
            #pragma unroll
            for (int r = 0; r < 4; r++) acc[mt][nt][r] = 0.f;

    const int mat = lane >> 3, lr = lane & 7;
    const int a_roff = (mat & 1) * 8 + lr;
    const int a_coff = (mat >> 1) * 8;
    const int b_roff = (mat >> 1) * 8 + lr;
    const int b_coff = (mat & 1) * 8;

    hmma_load_tile(sbase, Ah, Al, Bh, Bl, bm, bn, 0, tid);
    CP_COMMIT();

    for (int kc = 0; kc < KD / 32; kc++) {
        const uint32_t sbuf = sbase + (uint32_t)(kc & 1) * BUFB;
        if (kc + 1 < KD / 32) {
            hmma_load_tile(sbase + (uint32_t)((kc + 1) & 1) * BUFB,
                           Ah, Al, Bh, Bl, bm, bn, (kc + 1) * 32, tid);
            CP_COMMIT();
            CP_WAIT(1);
        } else {
            CP_WAIT(0);
        }
        __syncthreads();

        #pragma unroll
        for (int kk = 0; kk < 32; kk += 16) {
            uint32_t ahi[4][4], alo[4][4];
            #pragma unroll
            for (int mt = 0; mt < 4; mt++) {
                uint32_t ad = sbuf + SA_H +
                    (uint32_t)((wm * 64 + mt * 16 + a_roff) * STR + kk + a_coff) * 2;
                LDMX4(ahi[mt][0], ahi[mt][1], ahi[mt][2], ahi[mt][3], ad);
                LDMX4(alo[mt][0], alo[mt][1], alo[mt][2], alo[mt][3], ad + (SA_L - SA_H));
            }
            uint32_t bhi[4][2], blo[4][2];
            #pragma unroll
            for (int g = 0; g < 2; g++) {
                uint32_t bd = sbuf + SB_H +
                    (uint32_t)((wn * 32 + g * 16 + b_roff) * STR + kk + b_coff) * 2;
                LDMX4(bhi[g*2][0], bhi[g*2][1], bhi[g*2+1][0], bhi[g*2+1][1], bd);
                LDMX4(blo[g*2][0], blo[g*2][1], blo[g*2+1][0], blo[g*2+1][1],
                      bd + (SB_L - SB_H));
            }
            #pragma unroll
            for (int mt = 0; mt < 4; mt++)
                #pragma unroll
                for (int nt = 0; nt < 4; nt++) {
                    mma16816(acc[mt][nt], ahi[mt], bhi[nt]);
                    mma16816(acc[mt][nt], ahi[mt], blo[nt]);
                    mma16816(acc[mt][nt], alo[mt], bhi[nt]);
                }
        }
        __syncthreads();
    }

    #pragma unroll
    for (int mt = 0; mt < 4; mt++) {
        #pragma unroll
        for (int nt = 0; nt < 4; nt++) {
            int row = bm + wm * 64 + mt * 16 + (lane >> 2);
            int col = bn + wn * 32 + nt * 8 + (lane & 3) * 2;
            float b0 = bias[col], b1 = bias[col + 1];
            float2 v0 = make_float2(acc[mt][nt][0] + b0, acc[mt][nt][1] + b1);
            float2 v1 = make_float2(acc[mt][nt][2] + b0, acc[mt][nt][3] + b1);
            *(float2*)(C + (size_t)row * EMBED + col) = v0;
            *(float2*)(C + (size_t)(row + 8) * EMBED + col) = v1;
        }
    }
}

__global__ __launch_bounds__(256, 1)
void qkv_hmma_kernel(const float* __restrict__ bq, const float* __restrict__ bk,
                     const float* __restrict__ bv)
{
    const int z = blockIdx.z;
    const float* bias = (z == 0) ? bq : (z == 1) ? bk : bv;
    hmma_gemm_body(g_xh, g_xl,
                   g_wth + (size_t)z * EMBED * EMBED, g_wtl + (size_t)z * EMBED * EMBED,
                   bias, g_QKV + (size_t)z * M_QKV * EMBED);
}

__global__ __launch_bounds__(256, 1)
void out_hmma_kernel(const float* __restrict__ bo, float* __restrict__ out)
{
    hmma_gemm_body(g_ah, g_al,
                   g_wth + (size_t)3 * EMBED * EMBED, g_wtl + (size_t)3 * EMBED * EMBED,
                   bo, out);
}

// ---------------- conversion kernels ---------------------------------------
__global__ __launch_bounds__(256)
void conv_x_kernel(const float* __restrict__ s)
{
    int i = blockIdx.x * 256 + threadIdx.x;
    float4 v = ((const float4*)s)[i];
    union { __nv_bfloat16 b[4]; uint2 u; } H, L;
    float f[4] = {v.x, v.y, v.z, v.w};
    #pragma unroll
    for (int j = 0; j < 4; j++) {
        H.b[j] = __float2bfloat16(f[j]);
        L.b[j] = __float2bfloat16(f[j] - __bfloat162float(H.b[j]));
    }
    ((uint2*)g_xh)[i] = H.u;
    ((uint2*)g_xl)[i] = L.u;
}

__global__ __launch_bounds__(256)
void conv_a_kernel()
{
    int i = blockIdx.x * 256 + threadIdx.x;
    float4 v = ((const float4*)g_A)[i];
    union { __nv_bfloat16 b[4]; uint2 u; } H, L;
    float f[4] = {v.x, v.y, v.z, v.w};
    #pragma unroll
    for (int j = 0; j < 4; j++) {
        H.b[j] = __float2bfloat16(f[j]);
        L.b[j] = __float2bfloat16(f[j] - __bfloat162float(H.b[j]));
    }
    ((uint2*)g_ah)[i] = H.u;
    ((uint2*)g_al)[i] = L.u;
}

__global__ __launch_bounds__(256)
void conv_w_kernel(const float* __restrict__ Wq, const float* __restrict__ Wk,
                   const float* __restrict__ Wv, const float* __restrict__ Wo)
{
    __shared__ float t[32][33];
    const int z = blockIdx.z;
    const float* W = (z == 0) ? Wq : (z == 1) ? Wk : (z == 2) ? Wv : Wo;
    const int n0 = blockIdx.x * 32, k0 = blockIdx.y * 32;
    const int tx = threadIdx.x, ty = threadIdx.y;
    #pragma unroll
    for (int i = 0; i < 4; i++)
        t[ty + i*8][tx] = W[(size_t)(k0 + ty + i*8) * EMBED + n0 + tx];
    __syncthreads();
    #pragma unroll
    for (int i = 0; i < 4; i++) {
        int n = n0 + ty + i*8, k = k0 + tx;
        float v = t[tx][ty + i*8];
        __nv_bfloat16 hv = __float2bfloat16(v);
        size_t o = (size_t)z * EMBED * EMBED + (size_t)n * EMBED + k;
        g_wth[o] = hv;
        g_wtl[o] = __float2bfloat16(v - __bfloat162float(hv));
    }
}

// ---------------- head split + seq maxpool(2) + bf16 split ------------------
__global__ __launch_bounds__(256)
void pool_kernel()
{
    int idx = blockIdx.x * 256 + threadIdx.x;
    int c4 = idx & 15;
    int sp = (idx >> 4) & 2047;
    int n  = (idx >> 15) & 63;
    int z  = idx >> 21;
    int b = n >> 4, h = n & 15;
    const float* src = g_QKV + (size_t)z * M_QKV * EMBED
                     + (size_t)(b * SEQ + 2 * sp) * EMBED + h * HD + c4 * 4;
    float4 u = *(const float4*)src;
    float4 w = *(const float4*)(src + EMBED);
    float f[4];
    f[0] = fmaxf(u.x, w.x); f[1] = fmaxf(u.y, w.y);
    f[2] = fmaxf(u.z, w.z); f[3] = fmaxf(u.w, w.w);
    if (z == 0) {  // q gets the 1/sqrt(hd) scale (exact power of two)
        #pragma unroll
        for (int j = 0; j < 4; j++) f[j] *= 0.125f;
    }
    union { __nv_bfloat16 b[4]; uint2 u; } H, L;
    #pragma unroll
    for (int j = 0; j < 4; j++) {
        H.b[j] = __float2bfloat16(f[j]);
        L.b[j] = __float2bfloat16(f[j] - __bfloat162float(H.b[j]));
    }
    __nv_bfloat16* dh = (z == 0) ? g_qh : (z == 1) ? g_kh : g_vh;
    __nv_bfloat16* dl = (z == 0) ? g_ql : (z == 1) ? g_kl : g_vl;
    size_t o = ((size_t)n * SP + sp) * HD + c4 * 4;
    *(uint2*)(dh + o) = H.u;
    *(uint2*)(dl + o) = L.u;
}

// ---------------- HMMA flash attention + final maxpool ----------------------
#define ASTR 72                     /* padded smem stride (elems): 9 x 16B */
#define QLOFF 18432                 /* 128*72*2 */
#define KVOFF 36864
#define TILEB 9216                  /* 64*72*2 */
#define KVBUF 36864                 /* 4 tiles */
#define SMEM_AT (KVOFF + 2*KVBUF)   /* 110592 */

__device__ __forceinline__ void attn_load_kv(uint32_t sbase, int n, int kt,
                                             int buf, int tid)
{
    uint32_t base = sbase + KVOFF + (uint32_t)buf * KVBUF;
    #pragma unroll
    for (int i = 0; i < 8; i++) {
        int idx = tid + i * 256;
        int arr = idx >> 9, r = (idx >> 3) & 63, c = idx & 7;
        const __nv_bfloat16* sb = (arr == 0) ? g_kh : (arr == 1) ? g_kl
                                 : (arr == 2) ? g_vh : g_vl;
        const __nv_bfloat16* src = sb + ((size_t)n * SP + kt * 64 + r) * HD + c * 8;
        CP_ASYNC16(base + (uint32_t)arr * TILEB + (uint32_t)(r * ASTR + c * 8) * 2, src);
    }
}

__global__ __launch_bounds__(256)
void attn_kernel()
{
    extern __shared__ char smem[];
    const uint32_t sbase = smem_u32(smem);
    const int tid = threadIdx.x, lane = tid & 31, w = tid >> 5;
    const int n = blockIdx.y, Q0 = blockIdx.x * 128;
    const int lr = lane & 7, mat = lane >> 3;
    const int a_roff = (mat & 1) * 8 + lr, a_coff = (mat >> 1) * 8;
    const int b_roff = (mat >> 1) * 8 + lr, b_coff = (mat & 1) * 8;
    const int v_roff = (mat & 1) * 8 + lr, v_coff = (mat >> 1) * 8;

    // load Q tile (hi+lo): 2048 16B chunks
    #pragma unroll
    for (int i = 0; i < 8; i++) {
        int idx = tid + i * 256;
        int arr = idx >> 10, r = (idx >> 3) & 127, c = idx & 7;
        const __nv_bfloat16* src = (arr ? g_ql : g_qh)
                                 + ((size_t)n * SP + Q0 + r) * HD + c * 8;
        CP_ASYNC16(sbase + (uint32_t)arr * QLOFF + (uint32_t)(r * ASTR + c * 8) * 2, src);
    }
    attn_load_kv(sbase, n, 0, 0, tid);
    CP_COMMIT();

    float Sv[8][4], O[8][4];
    float m1 = -CUDART_INF_F, m2 = -CUDART_INF_F, l1 = 0.f, l2 = 0.f;
    #pragma unroll
    for (int t = 0; t < 8; t++)
        #pragma unroll
        for (int r = 0; r < 4; r++) O[t][r] = 0.f;

    for (int kt = 0; kt < SP / 64; kt++) {
        if (kt + 1 < SP / 64) {
            attn_load_kv(sbase, n, kt + 1, (kt + 1) & 1, tid);
            CP_COMMIT();
            CP_WAIT(1);
        } else {
            CP_WAIT(0);
        }
        __syncthreads();
        const uint32_t kb = sbase + KVOFF + (uint32_t)(kt & 1) * KVBUF;

        // ---- S = Q K^T (split-bf16, 3 terms) ----
        #pragma unroll
        for (int t = 0; t < 8; t++)
            #pragma unroll
            for (int r = 0; r < 4; r++) Sv[t][r] = 0.f;

        #pragma unroll
        for (int k4 = 0; k4 < 4; k4++) {
            uint32_t aqh[4], aql[4];
            uint32_t qa = sbase + (uint32_t)((w * 16 + a_roff) * ASTR + k4 * 16 + a_coff) * 2;
            LDMX4(aqh[0], aqh[1], aqh[2], aqh[3], qa);
            LDMX4(aql[0], aql[1], aql[2], aql[3], qa + QLOFF);
            uint32_t khf[8][2], klf[8][2];
            #pragma unroll
            for (int g = 0; g < 4; g++) {
                uint32_t ka = kb + (uint32_t)((g * 16 + b_roff) * ASTR + k4 * 16 + b_coff) * 2;
                LDMX4(khf[2*g][0], khf[2*g][1], khf[2*g+1][0], khf[2*g+1][1], ka);
                LDMX4(klf[2*g][0], klf[2*g][1], klf[2*g+1][0], klf[2*g+1][1], ka + TILEB);
            }
            #pragma unroll
            for (int t = 0; t < 8; t++) {
                mma16816(Sv[t], aqh, khf[t]);
                mma16816(Sv[t], aqh, klf[t]);
                mma16816(Sv[t], aql, khf[t]);
            }
        }

        // ---- online softmax (rows r1=lane/4, r2=r1+8) ----
        float mx1 = -CUDART_INF_F, mx2 = -CUDART_INF_F;
        #pragma unroll
        for (int t = 0; t < 8; t++) {
            mx1 = fmaxf(mx1, fmaxf(Sv[t][0], Sv[t][1]));
            mx2 = fmaxf(mx2, fmaxf(Sv[t][2], Sv[t][3]));
        }
        mx1 = fmaxf(mx1, __shfl_xor_sync(0xffffffffu, mx1, 1));
        mx1 = fmaxf(mx1, __shfl_xor_sync(0xffffffffu, mx1, 2));
        mx2 = fmaxf(mx2, __shfl_xor_sync(0xffffffffu, mx2, 1));
        mx2 = fmaxf(mx2, __shfl_xor_sync(0xffffffffu, mx2, 2));
        float mn1 = fmaxf(m1, mx1), mn2 = fmaxf(m2, mx2);
        float al1 = __expf(m1 - mn1), al2 = __expf(m2 - mn2);
        m1 = mn1; m2 = mn2;
        float rs1 = 0.f, rs2 = 0.f;
        #pragma unroll
        for (int t = 0; t < 8; t++) {
            Sv[t][0] = __expf(Sv[t][0] - mn1);
            Sv[t][1] = __expf(Sv[t][1] - mn1);
            Sv[t][2] = __expf(Sv[t][2] - mn2);
            Sv[t][3] = __expf(Sv[t][3] - mn2);
            rs1 += Sv[t][0] + Sv[t][1];
            rs2 += Sv[t][2] + Sv[t][3];
        }
        rs1 += __shfl_xor_sync(0xffffffffu, rs1, 1);
        rs1 += __shfl_xor_sync(0xffffffffu, rs1, 2);
        rs2 += __shfl_xor_sync(0xffffffffu, rs2, 1);
        rs2 += __shfl_xor_sync(0xffffffffu, rs2, 2);
        l1 = l1 * al1 + rs1;
        l2 = l2 * al2 + rs2;
        #pragma unroll
        for (int t = 0; t < 8; t++) {
            O[t][0] *= al1; O[t][1] *= al1;
            O[t][2] *= al2; O[t][3] *= al2;
        }

        // ---- O += P V (split-bf16, 3 terms; P built in registers) ----
        #pragma unroll
        for (int jj = 0; jj < 4; jj++) {
            uint32_t ph[4], pl[4];
            pack_split(Sv[2*jj][0],   Sv[2*jj][1],   ph[0], pl[0]);
            pack_split(Sv[2*jj][2],   Sv[2*jj][3],   ph[1], pl[1]);
            pack_split(Sv[2*jj+1][0], Sv[2*jj+1][1], ph[2], pl[2]);
            pack_split(Sv[2*jj+1][2], Sv[2*jj+1][3], ph[3], pl[3]);
            uint32_t vhf[8][2], vlf[8][2];
            #pragma unroll
            for (int g = 0; g < 4; g++) {
                uint32_t va = kb + 2 * TILEB +
                    (uint32_t)((jj * 16 + v_roff) * ASTR + g * 16 + v_coff) * 2;
                LDMX4T(vhf[2*g][0], vhf[2*g][1], vhf[2*g+1][0], vhf[2*g+1][1], va);
                LDMX4T(vlf[2*g][0], vlf[2*g][1], vlf[2*g+1][0], vlf[2*g+1][1], va + TILEB);
            }
            #pragma unroll
            for (int t = 0; t < 8; t++) {
                mma16816(O[t], ph, vhf[t]);
                mma16816(O[t], ph, vlf[t]);
                mma16816(O[t], pl, vhf[t]);
            }
        }
        __syncthreads();
    }

    // ---- epilogue: /l, q-pair maxpool via shfl, write head-major g_A ----
    const float inv1 = 1.f / l1, inv2 = 1.f / l2;
    const int prow1 = Q0 / 2 + w * 8 + (lane >> 3);        // valid for even group
    const int prow2 = prow1 + 4;
    #pragma unroll
    for (int t = 0; t < 8; t++) {
        float o0 = O[t][0] * inv1, o1 = O[t][1] * inv1;
        float o2 = O[t][2] * inv2, o3 = O[t][3] * inv2;
        float p0 = __shfl_xor_sync(0xffffffffu, o0, 4);
        float p1 = __shfl_xor_sync(0xffffffffu, o1, 4);
        float p2 = __shfl_xor_sync(0xffffffffu, o2, 4);
        float p3 = __shfl_xor_sync(0xffffffffu, o3, 4);
        if ((lane & 4) == 0) {
            int col = t * 8 + (lane & 3) * 2;
            float2 w0 = make_float2(fmaxf(o0, p0), fmaxf(o1, p1));
            float2 w1 = make_float2(fmaxf(o2, p2), fmaxf(o3, p3));
            *(float2*)(g_A + ((size_t)n * SQ4 + prow1) * HD + col) = w0;
            *(float2*)(g_A + ((size_t)n * SQ4 + prow2) * HD + col) = w1;
        }
    }
}

// ---------------- launch ----------------------------------------------------
extern "C" void kernel_launch(void* const* d_in, const int* in_sizes, int n_in,
                              void* d_out, int out_size)
{
    const float* x  = (const float*)d_in[0];
    const float* Wq = (const float*)d_in[1];
    const float* bq = (const float*)d_in[2];
    const float* Wk = (const float*)d_in[3];
    const float* bk = (const float*)d_in[4];
    const float* Wv = (const float*)d_in[5];
    const float* bv = (const float*)d_in[6];
    const float* Wo = (const float*)d_in[7];
    const float* bo = (const float*)d_in[8];
    float* out = (float*)d_out;

    cudaFuncSetAttribute(attn_kernel,
                         cudaFuncAttributeMaxDynamicSharedMemorySize, SMEM_AT);
    cudaFuncSetAttribute(qkv_hmma_kernel,
                         cudaFuncAttributeMaxDynamicSharedMemorySize, SMEM_HM);
    cudaFuncSetAttribute(out_hmma_kernel,
                         cudaFuncAttributeMaxDynamicSharedMemorySize, SMEM_HM);

    // 1. split-convert x; transpose+split weights
    conv_x_kernel<<<(M_QKV * EMBED / 4) / 256, 256>>>(x);
    conv_w_kernel<<<dim3(32, 32, 4), dim3(32, 8)>>>(Wq, Wk, Wv, Wo);

    // 2. QKV projection on tensor cores
    qkv_hmma_kernel<<<dim3(EMBED / 128, M_QKV / 128, 3), 256, SMEM_HM>>>(bq, bk, bv);

    // 3. head split + pool + bf16 split
    pool_kernel<<<(3 * NPOOL * SP * (HD / 4)) / 256, 256>>>();

    // 4. HMMA flash attention + final pool
    attn_kernel<<<dim3(SP / 128, NPOOL), 256, SMEM_AT>>>();

    // 5. convert attn output; output projection on tensor cores
    conv_a_kernel<<<(BATCH * SQ4 * EMBED / 4) / 256, 256>>>();
    out_hmma_kernel<<<dim3(EMBED / 128, (BATCH * SQ4) / 128), 256, SMEM_HM>>>(bo, out);
}

// round 8
// speedup vs baseline: 3.5892x; 1.3101x over previous
#include <cuda_runtime.h>
#include <cuda_bf16.h>
#include <math_constants.h>
#include <cstdint>

#define EMBED 1024
#define BATCH 4
#define SEQ 4096
#define NHEAD 16
#define HD 64
#define M_QKV 16384
#define NPOOL 64
#define SP 2048
#define SQ4 1024

// ---------------- packed scratch ----------------
// x A-pack: [kc(16)][m(16384)][64] bf16, chunks swizzled by (m&7)
__device__ __nv_bfloat16 g_xp_h[(size_t)M_QKV*EMBED];
__device__ __nv_bfloat16 g_xp_l[(size_t)M_QKV*EMBED];
// W B-pack: [z(4)][kc(16)][n(1024)][64], swizzled by (n&7)
__device__ __nv_bfloat16 g_wp_h[(size_t)4*EMBED*EMBED];
__device__ __nv_bfloat16 g_wp_l[(size_t)4*EMBED*EMBED];
// pooled q/k/v: [n(64)][sp(2048)][64], swizzled by (sp&7)
__device__ __nv_bfloat16 g_qp_h[(size_t)NPOOL*SP*HD];
__device__ __nv_bfloat16 g_qp_l[(size_t)NPOOL*SP*HD];
__device__ __nv_bfloat16 g_kp_h[(size_t)NPOOL*SP*HD];
__device__ __nv_bfloat16 g_kp_l[(size_t)NPOOL*SP*HD];
__device__ __nv_bfloat16 g_vp_h[(size_t)NPOOL*SP*HD];
__device__ __nv_bfloat16 g_vp_l[(size_t)NPOOL*SP*HD];
// attn-out A-pack: [kc(16)][m(4096)][64], swizzled by (m&7)
__device__ __nv_bfloat16 g_ap_h[(size_t)4*SQ4*EMBED];
__device__ __nv_bfloat16 g_ap_l[(size_t)4*SQ4*EMBED];

// ---------------- PTX helpers ----------------
__device__ __forceinline__ uint32_t smem_u32(const void* p) {
    uint32_t a;
    asm("{ .reg .u64 t; cvta.to.shared.u64 t, %1; cvt.u32.u64 %0, t; }" : "=r"(a) : "l"(p));
    return a;
}
#define MBAR_INIT(mb, c) \
    asm volatile("mbarrier.init.shared.b64 [%0], %1;" :: "r"(mb), "r"((uint32_t)(c)) : "memory")
#define MBAR_EXPECT(mb, n) \
    asm volatile("mbarrier.arrive.expect_tx.shared.b64 _, [%0], %1;" :: "r"(mb), "r"((uint32_t)(n)) : "memory")
#define BULK_G2S(dst, src, bytes, mb) \
    asm volatile("cp.async.bulk.shared::cta.global.mbarrier::complete_tx::bytes [%0], [%1], %2, [%3];" \
        :: "r"(dst), "l"(src), "r"((uint32_t)(bytes)), "r"(mb) : "memory")
#define MBAR_WAIT(mb, ph) do { \
    uint32_t _mb = (mb), _ph = (ph), _done; \
    asm volatile("{\n\t.reg .pred p;\n\t" \
        "mbarrier.try_wait.parity.acquire.cta.shared::cta.b64 p, [%1], %2;\n\t" \
        "selp.b32 %0, 1, 0, p;\n\t}" : "=r"(_done) : "r"(_mb), "r"(_ph) : "memory"); \
    if (!_done) { \
        asm volatile("{\n\t.reg .pred P1;\n\t" \
            "WL_%=:\n\t" \
            "mbarrier.try_wait.parity.acquire.cta.shared::cta.b64 P1, [%0], %1, 0x989680;\n\t" \
            "@P1 bra.uni WD_%=;\n\t" \
            "bra.uni WL_%=;\n\t" \
            "WD_%=:\n\t}" :: "r"(_mb), "r"(_ph) : "memory"); \
    } \
} while(0)
#define LDMX4(d0, d1, d2, d3, a) \
    asm volatile("ldmatrix.sync.aligned.m8n8.x4.shared.b16 {%0,%1,%2,%3}, [%4];" \
                 : "=r"(d0), "=r"(d1), "=r"(d2), "=r"(d3) : "r"(a))
#define LDMX4T(d0, d1, d2, d3, a) \
    asm volatile("ldmatrix.sync.aligned.m8n8.x4.trans.shared.b16 {%0,%1,%2,%3}, [%4];" \
                 : "=r"(d0), "=r"(d1), "=r"(d2), "=r"(d3) : "r"(a))

__device__ __forceinline__ void mma16816(float* c, const uint32_t* a, const uint32_t* b) {
    asm volatile(
        "mma.sync.aligned.m16n8k16.row.col.f32.bf16.bf16.f32 "
        "{%0,%1,%2,%3}, {%4,%5,%6,%7}, {%8,%9}, {%0,%1,%2,%3};"
        : "+f"(c[0]), "+f"(c[1]), "+f"(c[2]), "+f"(c[3])
        : "r"(a[0]), "r"(a[1]), "r"(a[2]), "r"(a[3]), "r"(b[0]), "r"(b[1]));
}
__device__ __forceinline__ void pack_split(float s0, float s1, uint32_t& h, uint32_t& l) {
    uint32_t hp;
    asm("cvt.rn.bf16x2.f32 %0, %1, %2;" : "=r"(hp) : "f"(s1), "f"(s0));
    float l0 = s0 - __uint_as_float(hp << 16);
    float l1 = s1 - __uint_as_float(hp & 0xffff0000u);
    h = hp;
    asm("cvt.rn.bf16x2.f32 %0, %1, %2;" : "=r"(l) : "f"(l1), "f"(l0));
}

// ================= GEMM (bulk 2-stage, K-chunk 64, tile 128x128) ===========
#define GSTG 65536
#define SMEM_GM (2*GSTG)

__device__ __forceinline__ void g_issue(uint32_t sbase, uint32_t mb0, int kc,
    const char* Ah, const char* Al, const char* Bh, const char* Bl,
    size_t Mtot, int bm, int bn)
{
    uint32_t mb = mb0 + (uint32_t)(kc & 1) * 8;
    uint32_t sb = sbase + (uint32_t)(kc & 1) * GSTG;
    size_t oa = ((size_t)kc * Mtot + bm) * 128;
    size_t ob = (((size_t)kc << 10) + bn) * 128;
    MBAR_EXPECT(mb, 65536);
    BULK_G2S(sb,         Ah + oa, 16384, mb);
    BULK_G2S(sb + 16384, Al + oa, 16384, mb);
    BULK_G2S(sb + 32768, Bh + ob, 16384, mb);
    BULK_G2S(sb + 49152, Bl + ob, 16384, mb);
}

__device__ __forceinline__ void gemm_mainloop(
    const char* Ah, const char* Al, const char* Bh, const char* Bl,
    size_t Mtot, int bm, int bn, char* smem, uint64_t* mbars,
    float acc[4][4][4])
{
    const uint32_t sbase = smem_u32(smem), mb0 = smem_u32(mbars);
    const int tid = threadIdx.x, lane = tid & 31, wid = tid >> 5;
    const int wm = wid & 1, wn = wid >> 1;
    const int lr = lane & 7, mat = lane >> 3;
    const int a_roff = (mat & 1) * 8 + lr;
    const int b_roff = (mat >> 1) * 8 + lr;

    #pragma unroll
    for (int mt = 0; mt < 4; mt++)
        #pragma unroll
        for (int nt = 0; nt < 4; nt++)
            #pragma unroll
            for (int r = 0; r < 4; r++) acc[mt][nt][r] = 0.f;

    if (tid == 0) { MBAR_INIT(mb0, 1); MBAR_INIT(mb0 + 8, 1); }
    __syncthreads();
    if (tid == 0) {
        g_issue(sbase, mb0, 0, Ah, Al, Bh, Bl, Mtot, bm, bn);
        g_issue(sbase, mb0, 1, Ah, Al, Bh, Bl, Mtot, bm, bn);
    }

    for (int kc = 0; kc < 16; kc++) {
        MBAR_WAIT(mb0 + (uint32_t)(kc & 1) * 8, (kc >> 1) & 1);
        const uint32_t sb = sbase + (uint32_t)(kc & 1) * GSTG;

        #pragma unroll
        for (int ks = 0; ks < 4; ks++) {
            uint32_t ahi[4][4], alo[4][4];
            #pragma unroll
            for (int mt = 0; mt < 4; mt++) {
                int r = wm * 64 + mt * 16 + a_roff;
                int ck = ks * 2 + (mat >> 1);
                uint32_t ad = sb + (uint32_t)(r * 128 + ((ck ^ (r & 7)) << 4));
                LDMX4(ahi[mt][0], ahi[mt][1], ahi[mt][2], ahi[mt][3], ad);
                LDMX4(alo[mt][0], alo[mt][1], alo[mt][2], alo[mt][3], ad + 16384);
            }
            uint32_t bhi[4][2], blo[4][2];
            #pragma unroll
            for (int g = 0; g < 2; g++) {
                int rb = wn * 32 + g * 16 + b_roff;
                int ck = ks * 2 + (mat & 1);
                uint32_t bd = sb + 32768 + (uint32_t)(rb * 128 + ((ck ^ (rb & 7)) << 4));
                LDMX4(bhi[2*g][0], bhi[2*g][1], bhi[2*g+1][0], bhi[2*g+1][1], bd);
                LDMX4(blo[2*g][0], blo[2*g][1], blo[2*g+1][0], blo[2*g+1][1], bd + 16384);
            }
            #pragma unroll
            for (int mt = 0; mt < 4; mt++)
                #pragma unroll
                for (int nt = 0; nt < 4; nt++) {
                    mma16816(acc[mt][nt], ahi[mt], bhi[nt]);
                    mma16816(acc[mt][nt], ahi[mt], blo[nt]);
                    mma16816(acc[mt][nt], alo[mt], bhi[nt]);
                }
        }
        __syncthreads();
        if (tid == 0 && kc + 2 < 16)
            g_issue(sbase, mb0, kc + 2, Ah, Al, Bh, Bl, Mtot, bm, bn);
    }
}

// QKV: mainloop + fused bias/maxpool/split/packed q,k,v write
__global__ __launch_bounds__(256, 1)
void qkv_hmma_kernel(const float* __restrict__ bq, const float* __restrict__ bk,
                     const float* __restrict__ bv)
{
    extern __shared__ __align__(128) char smem[];
    __shared__ uint64_t mbars[2];
    const int z = blockIdx.z;
    const float* bias = (z == 0) ? bq : (z == 1) ? bk : bv;
    const int bm = blockIdx.y * 128, bn = blockIdx.x * 128;

    float acc[4][4][4];
    gemm_mainloop((const char*)g_xp_h, (const char*)g_xp_l,
                  (const char*)g_wp_h + ((size_t)z << 21),
                  (const char*)g_wp_l + ((size_t)z << 21),
                  M_QKV, bm, bn, smem, mbars, acc);

    const int tid = threadIdx.x, lane = tid & 31, wid = tid >> 5;
    const int wm = wid & 1, wn = wid >> 1;
    char* dh = (char*)((z == 0) ? g_qp_h : (z == 1) ? g_kp_h : g_vp_h);
    char* dl = (char*)((z == 0) ? g_qp_l : (z == 1) ? g_kp_l : g_vp_l);
    const float qs = (z == 0) ? 0.125f : 1.0f;

    #pragma unroll
    for (int mt = 0; mt < 4; mt++) {
        #pragma unroll
        for (int nt = 0; nt < 4; nt++) {
            int m = bm + wm * 64 + mt * 16 + (lane >> 2);
            int gcol = bn + wn * 32 + nt * 8 + (lane & 3) * 2;
            float b0 = bias[gcol], b1 = bias[gcol + 1];
            float v00 = (acc[mt][nt][0] + b0) * qs, v01 = (acc[mt][nt][1] + b1) * qs;
            float v10 = (acc[mt][nt][2] + b0) * qs, v11 = (acc[mt][nt][3] + b1) * qs;
            float p00 = __shfl_xor_sync(0xffffffffu, v00, 4);
            float p01 = __shfl_xor_sync(0xffffffffu, v01, 4);
            float p10 = __shfl_xor_sync(0xffffffffu, v10, 4);
            float p11 = __shfl_xor_sync(0xffffffffu, v11, 4);
            if ((lane & 4) == 0) {
                int sp = (m & 4095) >> 1;
                int n = (m >> 12) * NHEAD + (gcol >> 6);
                int d = gcol & 63;
                uint32_t h0, l0, h1, l1;
                pack_split(fmaxf(v00, p00), fmaxf(v01, p01), h0, l0);
                pack_split(fmaxf(v10, p10), fmaxf(v11, p11), h1, l1);
                size_t a0 = ((size_t)(n * SP + sp)) * 128
                          + (((d >> 3) ^ (sp & 7)) << 4) + ((d & 7) << 1);
                size_t a1 = ((size_t)(n * SP + sp + 4)) * 128
                          + (((d >> 3) ^ ((sp + 4) & 7)) << 4) + ((d & 7) << 1);
                *(uint32_t*)(dh + a0) = h0; *(uint32_t*)(dl + a0) = l0;
                *(uint32_t*)(dh + a1) = h1; *(uint32_t*)(dl + a1) = l1;
            }
        }
    }
}

__global__ __launch_bounds__(256, 1)
void out_hmma_kernel(const float* __restrict__ bo, float* __restrict__ out)
{
    extern __shared__ __align__(128) char smem[];
    __shared__ uint64_t mbars[2];
    const int bm = blockIdx.y * 128, bn = blockIdx.x * 128;
    float acc[4][4][4];
    gemm_mainloop((const char*)g_ap_h, (const char*)g_ap_l,
                  (const char*)g_wp_h + ((size_t)3 << 21),
                  (const char*)g_wp_l + ((size_t)3 << 21),
                  4 * SQ4, bm, bn, smem, mbars, acc);

    const int tid = threadIdx.x, lane = tid & 31, wid = tid >> 5;
    const int wm = wid & 1, wn = wid >> 1;
    #pragma unroll
    for (int mt = 0; mt < 4; mt++) {
        #pragma unroll
        for (int nt = 0; nt < 4; nt++) {
            int row = bm + wm * 64 + mt * 16 + (lane >> 2);
            int col = bn + wn * 32 + nt * 8 + (lane & 3) * 2;
            float b0 = bo[col], b1 = bo[col + 1];
            *(float2*)(out + (size_t)row * EMBED + col) =
                make_float2(acc[mt][nt][0] + b0, acc[mt][nt][1] + b1);
            *(float2*)(out + (size_t)(row + 8) * EMBED + col) =
                make_float2(acc[mt][nt][2] + b0, acc[mt][nt][3] + b1);
        }
    }
}

// ---------------- packing kernels ----------------
__global__ __launch_bounds__(256)
void conv_x_kernel(const float* __restrict__ x)
{
    int idx = blockIdx.x * 256 + threadIdx.x;       // 2M threads: (kc, c, m)
    int m = idx & (M_QKV - 1);
    int c = (idx >> 14) & 7;
    int kc = idx >> 17;
    const float* src = x + (size_t)m * EMBED + kc * 64 + c * 8;
    union { __nv_bfloat16 b[8]; uint4 q; } H, L;
    #pragma unroll
    for (int j4 = 0; j4 < 2; j4++) {
        float4 f = *(const float4*)(src + j4 * 4);
        float fv[4] = {f.x, f.y, f.z, f.w};
        #pragma unroll
        for (int j = 0; j < 4; j++) {
            __nv_bfloat16 hv = __float2bfloat16(fv[j]);
            H.b[j4*4+j] = hv;
            L.b[j4*4+j] = __float2bfloat16(fv[j] - __bfloat162float(hv));
        }
    }
    size_t off = ((size_t)(kc * M_QKV + m)) * 128 + ((c ^ (m & 7)) << 4);
    *(uint4*)((char*)g_xp_h + off) = H.q;
    *(uint4*)((char*)g_xp_l + off) = L.q;
}

__global__ __launch_bounds__(256)
void conv_w_kernel(const float* __restrict__ Wq, const float* __restrict__ Wk,
                   const float* __restrict__ Wv, const float* __restrict__ Wo)
{
    __shared__ float t[64][65];
    const int z = blockIdx.z;
    const float* W = (z == 0) ? Wq : (z == 1) ? Wk : (z == 2) ? Wv : Wo;
    const int n0 = blockIdx.x * 64, k0 = blockIdx.y * 64;
    const int tid = threadIdx.x;
    #pragma unroll
    for (int i = 0; i < 16; i++) {
        int idx = tid + i * 256;
        t[idx >> 6][idx & 63] = W[(size_t)(k0 + (idx >> 6)) * EMBED + n0 + (idx & 63)];
    }
    __syncthreads();
    #pragma unroll
    for (int i = 0; i < 2; i++) {
        int o = tid + i * 256;
        int nl = o >> 3, c = o & 7;
        int n = n0 + nl;
        union { __nv_bfloat16 b[8]; uint4 q; } H, L;
        #pragma unroll
        for (int j = 0; j < 8; j++) {
            float v = t[c * 8 + j][nl];
            __nv_bfloat16 hv = __float2bfloat16(v);
            H.b[j] = hv;
            L.b[j] = __float2bfloat16(v - __bfloat162float(hv));
        }
        size_t off = ((size_t)((z * 16 + (k0 >> 6)) * EMBED + n)) * 128 + ((c ^ (n & 7)) << 4);
        *(uint4*)((char*)g_wp_h + off) = H.q;
        *(uint4*)((char*)g_wp_l + off) = L.q;
    }
}

// ================= attention (bulk 2-stage) =================
#define ASTG 32768
#define SMEM_AT (32768 + 2*ASTG)    /* Qh|Ql 32K + 2 stages = 96K */

__device__ __forceinline__ void a_issue(uint32_t sbase, uint32_t mb0, int kt, int n)
{
    uint32_t mb = mb0 + (uint32_t)(kt & 1) * 8;
    uint32_t sb = sbase + 32768 + (uint32_t)(kt & 1) * ASTG;
    size_t off = ((size_t)(n * SP + kt * 64)) * 128;
    MBAR_EXPECT(mb, 32768);
    BULK_G2S(sb,         (const char*)g_kp_h + off, 8192, mb);
    BULK_G2S(sb + 8192,  (const char*)g_kp_l + off, 8192, mb);
    BULK_G2S(sb + 16384, (const char*)g_vp_h + off, 8192, mb);
    BULK_G2S(sb + 24576, (const char*)g_vp_l + off, 8192, mb);
}

__global__ __launch_bounds__(256, 1)
void attn_kernel()
{
    extern __shared__ __align__(128) char smem[];
    __shared__ uint64_t ambars[3];
    const uint32_t sbase = smem_u32(smem), mb0 = smem_u32(ambars);
    const int tid = threadIdx.x, lane = tid & 31, w = tid >> 5;
    const int n = blockIdx.y, Q0 = blockIdx.x * 128;
    const int lr = lane & 7, mat = lane >> 3;
    const int a_roff = (mat & 1) * 8 + lr;
    const int b_roff = (mat >> 1) * 8 + lr;
    const int v_roff = (mat & 1) * 8 + lr;

    if (tid == 0) { MBAR_INIT(mb0, 1); MBAR_INIT(mb0 + 8, 1); MBAR_INIT(mb0 + 16, 1); }
    __syncthreads();
    if (tid == 0) {
        size_t oq = ((size_t)(n * SP + Q0)) * 128;
        MBAR_EXPECT(mb0 + 16, 32768);
        BULK_G2S(sbase,         (const char*)g_qp_h + oq, 16384, mb0 + 16);
        BULK_G2S(sbase + 16384, (const char*)g_qp_l + oq, 16384, mb0 + 16);
        a_issue(sbase, mb0, 0, n);
        a_issue(sbase, mb0, 1, n);
    }
    MBAR_WAIT(mb0 + 16, 0);

    float Sv[8][4], O[8][4];
    float m1 = -CUDART_INF_F, m2 = -CUDART_INF_F, l1 = 0.f, l2 = 0.f;
    #pragma unroll
    for (int t = 0; t < 8; t++)
        #pragma unroll
        for (int r = 0; r < 4; r++) O[t][r] = 0.f;

    for (int kt = 0; kt < SP / 64; kt++) {
        MBAR_WAIT(mb0 + (uint32_t)(kt & 1) * 8, (kt >> 1) & 1);
        const uint32_t kb = sbase + 32768 + (uint32_t)(kt & 1) * ASTG;

        #pragma unroll
        for (int t = 0; t < 8; t++)
            #pragma unroll
            for (int r = 0; r < 4; r++) Sv[t][r] = 0.f;

        #pragma unroll
        for (int k4 = 0; k4 < 4; k4++) {
            uint32_t aqh[4], aql[4];
            {
                int r = w * 16 + a_roff;
                int ck = k4 * 2 + (mat >> 1);
                uint32_t qa = sbase + (uint32_t)(r * 128 + ((ck ^ (r & 7)) << 4));
                LDMX4(aqh[0], aqh[1], aqh[2], aqh[3], qa);
                LDMX4(aql[0], aql[1], aql[2], aql[3], qa + 16384);
            }
            uint32_t khf[8][2], klf[8][2];
            #pragma unroll
            for (int g = 0; g < 4; g++) {
                int rk = g * 16 + b_roff;
                int ck = k4 * 2 + (mat & 1);
                uint32_t ka = kb + (uint32_t)(rk * 128 + ((ck ^ (rk & 7)) << 4));
                LDMX4(khf[2*g][0], khf[2*g][1], khf[2*g+1][0], khf[2*g+1][1], ka);
                LDMX4(klf[2*g][0], klf[2*g][1], klf[2*g+1][0], klf[2*g+1][1], ka + 8192);
            }
            #pragma unroll
            for (int t = 0; t < 8; t++) {
                mma16816(Sv[t], aqh, khf[t]);
                mma16816(Sv[t], aqh, klf[t]);
                mma16816(Sv[t], aql, khf[t]);
            }
        }

        float mx1 = -CUDART_INF_F, mx2 = -CUDART_INF_F;
        #pragma unroll
        for (int t = 0; t < 8; t++) {
            mx1 = fmaxf(mx1, fmaxf(Sv[t][0], Sv[t][1]));
            mx2 = fmaxf(mx2, fmaxf(Sv[t][2], Sv[t][3]));
        }
        mx1 = fmaxf(mx1, __shfl_xor_sync(0xffffffffu, mx1, 1));
        mx1 = fmaxf(mx1, __shfl_xor_sync(0xffffffffu, mx1, 2));
        mx2 = fmaxf(mx2, __shfl_xor_sync(0xffffffffu, mx2, 1));
        mx2 = fmaxf(mx2, __shfl_xor_sync(0xffffffffu, mx2, 2));
        float mn1 = fmaxf(m1, mx1), mn2 = fmaxf(m2, mx2);
        float al1 = __expf(m1 - mn1), al2 = __expf(m2 - mn2);
        m1 = mn1; m2 = mn2;
        float rs1 = 0.f, rs2 = 0.f;
        #pragma unroll
        for (int t = 0; t < 8; t++) {
            Sv[t][0] = __expf(Sv[t][0] - mn1);
            Sv[t][1] = __expf(Sv[t][1] - mn1);
            Sv[t][2] = __expf(Sv[t][2] - mn2);
            Sv[t][3] = __expf(Sv[t][3] - mn2);
            rs1 += Sv[t][0] + Sv[t][1];
            rs2 += Sv[t][2] + Sv[t][3];
        }
        rs1 += __shfl_xor_sync(0xffffffffu, rs1, 1);
        rs1 += __shfl_xor_sync(0xffffffffu, rs1, 2);
        rs2 += __shfl_xor_sync(0xffffffffu, rs2, 1);
        rs2 += __shfl_xor_sync(0xffffffffu, rs2, 2);
        l1 = l1 * al1 + rs1;
        l2 = l2 * al2 + rs2;
        #pragma unroll
        for (int t = 0; t < 8; t++) {
            O[t][0] *= al1; O[t][1] *= al1;
            O[t][2] *= al2; O[t][3] *= al2;
        }

        #pragma unroll
        for (int jj = 0; jj < 4; jj++) {
            uint32_t ph[4], pl[4];
            pack_split(Sv[2*jj][0],   Sv[2*jj][1],   ph[0], pl[0]);
            pack_split(Sv[2*jj][2],   Sv[2*jj][3],   ph[1], pl[1]);
            pack_split(Sv[2*jj+1][0], Sv[2*jj+1][1], ph[2], pl[2]);
            pack_split(Sv[2*jj+1][2], Sv[2*jj+1][3], ph[3], pl[3]);
            uint32_t vhf[8][2], vlf[8][2];
            #pragma unroll
            for (int g = 0; g < 4; g++) {
                int rv = jj * 16 + v_roff;
                int ck = g * 2 + (mat >> 1);
                uint32_t va = kb + 16384 + (uint32_t)(rv * 128 + ((ck ^ (rv & 7)) << 4));
                LDMX4T(vhf[2*g][0], vhf[2*g][1], vhf[2*g+1][0], vhf[2*g+1][1], va);
                LDMX4T(vlf[2*g][0], vlf[2*g][1], vlf[2*g+1][0], vlf[2*g+1][1], va + 8192);
            }
            #pragma unroll
            for (int t = 0; t < 8; t++) {
                mma16816(O[t], ph, vhf[t]);
                mma16816(O[t], ph, vlf[t]);
                mma16816(O[t], pl, vhf[t]);
            }
        }
        __syncthreads();
        if (tid == 0 && kt + 2 < SP / 64) a_issue(sbase, mb0, kt + 2, n);
    }

    // epilogue: /l, q-pair maxpool, write packed out-GEMM A operand
    const float inv1 = 1.f / l1, inv2 = 1.f / l2;
    const int prow1 = Q0 / 2 + w * 8 + (lane >> 3);
    const int prow2 = prow1 + 4;
    #pragma unroll
    for (int t = 0; t < 8; t++) {
        float o0 = O[t][0] * inv1, o1 = O[t][1] * inv1;
        float o2 = O[t][2] * inv2, o3 = O[t][3] * inv2;
        float p0 = __shfl_xor_sync(0xffffffffu, o0, 4);
        float p1 = __shfl_xor_sync(0xffffffffu, o1, 4);
        float p2 = __shfl_xor_sync(0xffffffffu, o2, 4);
        float p3 = __shfl_xor_sync(0xffffffffu, o3, 4);
        if ((lane & 4) == 0) {
            int d = t * 8 + (lane & 3) * 2;
            uint32_t h0, l0, h1, l1u;
            pack_split(fmaxf(o0, p0), fmaxf(o1, p1), h0, l0);
            pack_split(fmaxf(o2, p2), fmaxf(o3, p3), h1, l1u);
            int mrow1 = n * 64 + (prow1 >> 4), kc1 = prow1 & 15;
            int mrow2 = n * 64 + (prow2 >> 4), kc2 = prow2 & 15;
            size_t a0 = ((size_t)(kc1 * 4096 + mrow1)) * 128
                      + (((d >> 3) ^ (mrow1 & 7)) << 4) + ((d & 7) << 1);
            size_t a1 = ((size_t)(kc2 * 4096 + mrow2)) * 128
                      + (((d >> 3) ^ (mrow2 & 7)) << 4) + ((d & 7) << 1);
            *(uint32_t*)((char*)g_ap_h + a0) = h0;
            *(uint32_t*)((char*)g_ap_l + a0) = l0;
            *(uint32_t*)((char*)g_ap_h + a1) = h1;
            *(uint32_t*)((char*)g_ap_l + a1) = l1u;
        }
    }
}

// ---------------- launch ----------------
extern "C" void kernel_launch(void* const* d_in, const int* in_sizes, int n_in,
                              void* d_out, int out_size)
{
    const float* x  = (const float*)d_in[0];
    const float* Wq = (const float*)d_in[1];
    const float* bq = (const float*)d_in[2];
    const float* Wk = (const float*)d_in[3];
    const float* bk = (const float*)d_in[4];
    const float* Wv = (const float*)d_in[5];
    const float* bv = (const float*)d_in[6];
    const float* Wo = (const float*)d_in[7];
    const float* bo = (const float*)d_in[8];
    float* out = (float*)d_out;

    cudaFuncSetAttribute(qkv_hmma_kernel, cudaFuncAttributeMaxDynamicSharedMemorySize, SMEM_GM);
    cudaFuncSetAttribute(out_hmma_kernel, cudaFuncAttributeMaxDynamicSharedMemorySize, SMEM_GM);
    cudaFuncSetAttribute(attn_kernel,     cudaFuncAttributeMaxDynamicSharedMemorySize, SMEM_AT);

    conv_x_kernel<<<(M_QKV * EMBED / 8) / 256, 256>>>(x);
    conv_w_kernel<<<dim3(16, 16, 4), 256>>>(Wq, Wk, Wv, Wo);

    qkv_hmma_kernel<<<dim3(EMBED / 128, M_QKV / 128, 3), 256, SMEM_GM>>>(bq, bk, bv);

    attn_kernel<<<dim3(SP / 128, NPOOL), 256, SMEM_AT>>>();

    out_hmma_kernel<<<dim3(EMBED / 128, 4 * SQ4 / 128), 256, SMEM_GM>>>(bo, out);
}

// round 9
// speedup vs baseline: 3.5931x; 1.0011x over previous
#include <cuda_runtime.h>
#include <cuda_bf16.h>
#include <math_constants.h>
#include <cstdint>

#define EMBED 1024
#define BATCH 4
#define SEQ 4096
#define NHEAD 16
#define HD 64
#define M_QKV 16384
#define NPOOL 64
#define SP 2048
#define SQ4 1024

// ---------------- packed scratch ----------------
// x A-pack: [kc(16)][m(16384)][64] bf16, chunks swizzled by (m&7)
__device__ __nv_bfloat16 g_xp_h[(size_t)M_QKV*EMBED];
__device__ __nv_bfloat16 g_xp_l[(size_t)M_QKV*EMBED];
// W B-pack: [z(4)][kc(16)][n(1024)][64], swizzled by (n&7)
__device__ __nv_bfloat16 g_wp_h[(size_t)4*EMBED*EMBED];
__device__ __nv_bfloat16 g_wp_l[(size_t)4*EMBED*EMBED];
// pooled q/k/v: [n(64)][sp(2048)][64], swizzled by (sp&7)
__device__ __nv_bfloat16 g_qp_h[(size_t)NPOOL*SP*HD];
__device__ __nv_bfloat16 g_qp_l[(size_t)NPOOL*SP*HD];
__device__ __nv_bfloat16 g_kp_h[(size_t)NPOOL*SP*HD];
__device__ __nv_bfloat16 g_kp_l[(size_t)NPOOL*SP*HD];
__device__ __nv_bfloat16 g_vp_h[(size_t)NPOOL*SP*HD];
__device__ __nv_bfloat16 g_vp_l[(size_t)NPOOL*SP*HD];
// attn-out A-pack: [kc(16)][m(4096)][64], swizzled by (m&7)
__device__ __nv_bfloat16 g_ap_h[(size_t)4*SQ4*EMBED];
__device__ __nv_bfloat16 g_ap_l[(size_t)4*SQ4*EMBED];

// ---------------- PTX helpers ----------------
__device__ __forceinline__ uint32_t smem_u32(const void* p) {
    uint32_t a;
    asm("{ .reg .u64 t; cvta.to.shared.u64 t, %1; cvt.u32.u64 %0, t; }" : "=r"(a) : "l"(p));
    return a;
}
#define MBAR_INIT(mb, c) \
    asm volatile("mbarrier.init.shared.b64 [%0], %1;" :: "r"(mb), "r"((uint32_t)(c)) : "memory")
#define MBAR_EXPECT(mb, n) \
    asm volatile("mbarrier.arrive.expect_tx.shared.b64 _, [%0], %1;" :: "r"(mb), "r"((uint32_t)(n)) : "memory")
#define BULK_G2S(dst, src, bytes, mb) \
    asm volatile("cp.async.bulk.shared::cta.global.mbarrier::complete_tx::bytes [%0], [%1], %2, [%3];" \
        :: "r"(dst), "l"(src), "r"((uint32_t)(bytes)), "r"(mb) : "memory")
#define MBAR_WAIT(mb, ph) do { \
    uint32_t _mb = (mb), _ph = (ph), _done; \
    asm volatile("{\n\t.reg .pred p;\n\t" \
        "mbarrier.try_wait.parity.acquire.cta.shared::cta.b64 p, [%1], %2;\n\t" \
        "selp.b32 %0, 1, 0, p;\n\t}" : "=r"(_done) : "r"(_mb), "r"(_ph) : "memory"); \
    if (!_done) { \
        asm volatile("{\n\t.reg .pred P1;\n\t" \
            "WL_%=:\n\t" \
            "mbarrier.try_wait.parity.acquire.cta.shared::cta.b64 P1, [%0], %1, 0x989680;\n\t" \
            "@P1 bra.uni WD_%=;\n\t" \
            "bra.uni WL_%=;\n\t" \
            "WD_%=:\n\t}" :: "r"(_mb), "r"(_ph) : "memory"); \
    } \
} while(0)
#define LDMX4(d0, d1, d2, d3, a) \
    asm volatile("ldmatrix.sync.aligned.m8n8.x4.shared.b16 {%0,%1,%2,%3}, [%4];" \
                 : "=r"(d0), "=r"(d1), "=r"(d2), "=r"(d3) : "r"(a))
#define LDMX4T(d0, d1, d2, d3, a) \
    asm volatile("ldmatrix.sync.aligned.m8n8.x4.trans.shared.b16 {%0,%1,%2,%3}, [%4];" \
                 : "=r"(d0), "=r"(d1), "=r"(d2), "=r"(d3) : "r"(a))

__device__ __forceinline__ void mma16816(float* c, const uint32_t* a, const uint32_t* b) {
    asm volatile(
        "mma.sync.aligned.m16n8k16.row.col.f32.bf16.bf16.f32 "
        "{%0,%1,%2,%3}, {%4,%5,%6,%7}, {%8,%9}, {%0,%1,%2,%3};"
        : "+f"(c[0]), "+f"(c[1]), "+f"(c[2]), "+f"(c[3])
        : "r"(a[0]), "r"(a[1]), "r"(a[2]), "r"(a[3]), "r"(b[0]), "r"(b[1]));
}
__device__ __forceinline__ void pack_split(float s0, float s1, uint32_t& h, uint32_t& l) {
    uint32_t hp;
    asm("cvt.rn.bf16x2.f32 %0, %1, %2;" : "=r"(hp) : "f"(s1), "f"(s0));
    float l0 = s0 - __uint_as_float(hp << 16);
    float l1 = s1 - __uint_as_float(hp & 0xffff0000u);
    h = hp;
    asm("cvt.rn.bf16x2.f32 %0, %1, %2;" : "=r"(l) : "f"(l1), "f"(l0));
}

// ================= GEMM (bulk 2-stage, K-chunk 64, tile 128x128) ===========
#define GSTG 65536
#define SMEM_GM (2*GSTG)

__device__ __forceinline__ void g_issue(uint32_t sbase, uint32_t mb0, int kc,
    const char* Ah, const char* Al, const char* Bh, const char* Bl,
    size_t Mtot, int bm, int bn)
{
    uint32_t mb = mb0 + (uint32_t)(kc & 1) * 8;
    uint32_t sb = sbase + (uint32_t)(kc & 1) * GSTG;
    size_t oa = ((size_t)kc * Mtot + bm) * 128;
    size_t ob = (((size_t)kc << 10) + bn) * 128;
    MBAR_EXPECT(mb, 65536);
    BULK_G2S(sb,         Ah + oa, 16384, mb);
    BULK_G2S(sb + 16384, Al + oa, 16384, mb);
    BULK_G2S(sb + 32768, Bh + ob, 16384, mb);
    BULK_G2S(sb + 49152, Bl + ob, 16384, mb);
}

__device__ __forceinline__ void gemm_mainloop(
    const char* Ah, const char* Al, const char* Bh, const char* Bl,
    size_t Mtot, int bm, int bn, char* smem, uint64_t* mbars,
    float acc[4][4][4])
{
    const uint32_t sbase = smem_u32(smem), mb0 = smem_u32(mbars);
    const int tid = threadIdx.x, lane = tid & 31, wid = tid >> 5;
    const int wm = wid & 1, wn = wid >> 1;
    const int lr = lane & 7, mat = lane >> 3;
    const int a_roff = (mat & 1) * 8 + lr;
    const int b_roff = (mat >> 1) * 8 + lr;

    #pragma unroll
    for (int mt = 0; mt < 4; mt++)
        #pragma unroll
        for (int nt = 0; nt < 4; nt++)
            #pragma unroll
            for (int r = 0; r < 4; r++) acc[mt][nt][r] = 0.f;

    if (tid == 0) { MBAR_INIT(mb0, 1); MBAR_INIT(mb0 + 8, 1); }
    __syncthreads();
    if (tid == 0) {
        g_issue(sbase, mb0, 0, Ah, Al, Bh, Bl, Mtot, bm, bn);
        g_issue(sbase, mb0, 1, Ah, Al, Bh, Bl, Mtot, bm, bn);
    }

    for (int kc = 0; kc < 16; kc++) {
        MBAR_WAIT(mb0 + (uint32_t)(kc & 1) * 8, (kc >> 1) & 1);
        const uint32_t sb = sbase + (uint32_t)(kc & 1) * GSTG;

        #pragma unroll
        for (int ks = 0; ks < 4; ks++) {
            uint32_t ahi[4][4], alo[4][4];
            #pragma unroll
            for (int mt = 0; mt < 4; mt++) {
                int r = wm * 64 + mt * 16 + a_roff;
                int ck = ks * 2 + (mat >> 1);
                uint32_t ad = sb + (uint32_t)(r * 128 + ((ck ^ (r & 7)) << 4));
                LDMX4(ahi[mt][0], ahi[mt][1], ahi[mt][2], ahi[mt][3], ad);
                LDMX4(alo[mt][0], alo[mt][1], alo[mt][2], alo[mt][3], ad + 16384);
            }
            uint32_t bhi[4][2], blo[4][2];
            #pragma unroll
            for (int g = 0; g < 2; g++) {
                int rb = wn * 32 + g * 16 + b_roff;
                int ck = ks * 2 + (mat & 1);
                uint32_t bd = sb + 32768 + (uint32_t)(rb * 128 + ((ck ^ (rb & 7)) << 4));
                LDMX4(bhi[2*g][0], bhi[2*g][1], bhi[2*g+1][0], bhi[2*g+1][1], bd);
                LDMX4(blo[2*g][0], blo[2*g][1], blo[2*g+1][0], blo[2*g+1][1], bd + 16384);
            }
            #pragma unroll
            for (int mt = 0; mt < 4; mt++)
                #pragma unroll
                for (int nt = 0; nt < 4; nt++) {
                    mma16816(acc[mt][nt], ahi[mt], bhi[nt]);
                    mma16816(acc[mt][nt], ahi[mt], blo[nt]);
                    mma16816(acc[mt][nt], alo[mt], bhi[nt]);
                }
        }
        __syncthreads();
        if (tid == 0 && kc + 2 < 16)
            g_issue(sbase, mb0, kc + 2, Ah, Al, Bh, Bl, Mtot, bm, bn);
    }
}

// QKV: mainloop + fused bias/maxpool/split/packed q,k,v write
__global__ __launch_bounds__(256, 1)
void qkv_hmma_kernel(const float* __restrict__ bq, const float* __restrict__ bk,
                     const float* __restrict__ bv)
{
    extern __shared__ __align__(128) char smem[];
    __shared__ uint64_t mbars[2];
    const int z = blockIdx.z;
    const float* bias = (z == 0) ? bq : (z == 1) ? bk : bv;
    const int bm = blockIdx.y * 128, bn = blockIdx.x * 128;

    float acc[4][4][4];
    gemm_mainloop((const char*)g_xp_h, (const char*)g_xp_l,
                  (const char*)g_wp_h + ((size_t)z << 21),
                  (const char*)g_wp_l + ((size_t)z << 21),
                  M_QKV, bm, bn, smem, mbars, acc);

    const int tid = threadIdx.x, lane = tid & 31, wid = tid >> 5;
    const int wm = wid & 1, wn = wid >> 1;
    char* dh = (char*)((z == 0) ? g_qp_h : (z == 1) ? g_kp_h : g_vp_h);
    char* dl = (char*)((z == 0) ? g_qp_l : (z == 1) ? g_kp_l : g_vp_l);
    const float qs = (z == 0) ? 0.125f : 1.0f;

    #pragma unroll
    for (int mt = 0; mt < 4; mt++) {
        #pragma unroll
        for (int nt = 0; nt < 4; nt++) {
            int m = bm + wm * 64 + mt * 16 + (lane >> 2);
            int gcol = bn + wn * 32 + nt * 8 + (lane & 3) * 2;
            float b0 = bias[gcol], b1 = bias[gcol + 1];
            float v00 = (acc[mt][nt][0] + b0) * qs, v01 = (acc[mt][nt][1] + b1) * qs;
            float v10 = (acc[mt][nt][2] + b0) * qs, v11 = (acc[mt][nt][3] + b1) * qs;
            float p00 = __shfl_xor_sync(0xffffffffu, v00, 4);
            float p01 = __shfl_xor_sync(0xffffffffu, v01, 4);
            float p10 = __shfl_xor_sync(0xffffffffu, v10, 4);
            float p11 = __shfl_xor_sync(0xffffffffu, v11, 4);
            if ((lane & 4) == 0) {
                int sp = (m & 4095) >> 1;
                int n = (m >> 12) * NHEAD + (gcol >> 6);
                int d = gcol & 63;
                uint32_t h0, l0, h1, l1;
                pack_split(fmaxf(v00, p00), fmaxf(v01, p01), h0, l0);
                pack_split(fmaxf(v10, p10), fmaxf(v11, p11), h1, l1);
                size_t a0 = ((size_t)(n * SP + sp)) * 128
                          + (((d >> 3) ^ (sp & 7)) << 4) + ((d & 7) << 1);
                size_t a1 = ((size_t)(n * SP + sp + 4)) * 128
                          + (((d >> 3) ^ ((sp + 4) & 7)) << 4) + ((d & 7) << 1);
                *(uint32_t*)(dh + a0) = h0; *(uint32_t*)(dl + a0) = l0;
                *(uint32_t*)(dh + a1) = h1; *(uint32_t*)(dl + a1) = l1;
            }
        }
    }
}

__global__ __launch_bounds__(256, 1)
void out_hmma_kernel(const float* __restrict__ bo, float* __restrict__ out)
{
    extern __shared__ __align__(128) char smem[];
    __shared__ uint64_t mbars[2];
    const int bm = blockIdx.y * 128, bn = blockIdx.x * 128;
    float acc[4][4][4];
    gemm_mainloop((const char*)g_ap_h, (const char*)g_ap_l,
                  (const char*)g_wp_h + ((size_t)3 << 21),
                  (const char*)g_wp_l + ((size_t)3 << 21),
                  4 * SQ4, bm, bn, smem, mbars, acc);

    const int tid = threadIdx.x, lane = tid & 31, wid = tid >> 5;
    const int wm = wid & 1, wn = wid >> 1;
    #pragma unroll
    for (int mt = 0; mt < 4; mt++) {
        #pragma unroll
        for (int nt = 0; nt < 4; nt++) {
            int row = bm + wm * 64 + mt * 16 + (lane >> 2);
            int col = bn + wn * 32 + nt * 8 + (lane & 3) * 2;
            float b0 = bo[col], b1 = bo[col + 1];
            *(float2*)(out + (size_t)row * EMBED + col) =
                make_float2(acc[mt][nt][0] + b0, acc[mt][nt][1] + b1);
            *(float2*)(out + (size_t)(row + 8) * EMBED + col) =
                make_float2(acc[mt][nt][2] + b0, acc[mt][nt][3] + b1);
        }
    }
}

// ---------------- packing kernels ----------------
__global__ __launch_bounds__(256)
void conv_x_kernel(const float* __restrict__ x)
{
    int idx = blockIdx.x * 256 + threadIdx.x;       // 2M threads: (kc, c, m)
    int m = idx & (M_QKV - 1);
    int c = (idx >> 14) & 7;
    int kc = idx >> 17;
    const float* src = x + (size_t)m * EMBED + kc * 64 + c * 8;
    union { __nv_bfloat16 b[8]; uint4 q; } H, L;
    #pragma unroll
    for (int j4 = 0; j4 < 2; j4++) {
        float4 f = *(const float4*)(src + j4 * 4);
        float fv[4] = {f.x, f.y, f.z, f.w};
        #pragma unroll
        for (int j = 0; j < 4; j++) {
            __nv_bfloat16 hv = __float2bfloat16(fv[j]);
            H.b[j4*4+j] = hv;
            L.b[j4*4+j] = __float2bfloat16(fv[j] - __bfloat162float(hv));
        }
    }
    size_t off = ((size_t)(kc * M_QKV + m)) * 128 + ((c ^ (m & 7)) << 4);
    *(uint4*)((char*)g_xp_h + off) = H.q;
    *(uint4*)((char*)g_xp_l + off) = L.q;
}

__global__ __launch_bounds__(256)
void conv_w_kernel(const float* __restrict__ Wq, const float* __restrict__ Wk,
                   const float* __restrict__ Wv, const float* __restrict__ Wo)
{
    __shared__ float t[64][65];
    const int z = blockIdx.z;
    const float* W = (z == 0) ? Wq : (z == 1) ? Wk : (z == 2) ? Wv : Wo;
    const int n0 = blockIdx.x * 64, k0 = blockIdx.y * 64;
    const int tid = threadIdx.x;
    #pragma unroll
    for (int i = 0; i < 16; i++) {
        int idx = tid + i * 256;
        t[idx >> 6][idx & 63] = W[(size_t)(k0 + (idx >> 6)) * EMBED + n0 + (idx & 63)];
    }
    __syncthreads();
    #pragma unroll
    for (int i = 0; i < 2; i++) {
        int o = tid + i * 256;
        int nl = o >> 3, c = o & 7;
        int n = n0 + nl;
        union { __nv_bfloat16 b[8]; uint4 q; } H, L;
        #pragma unroll
        for (int j = 0; j < 8; j++) {
            float v = t[c * 8 + j][nl];
            __nv_bfloat16 hv = __float2bfloat16(v);
            H.b[j] = hv;
            L.b[j] = __float2bfloat16(v - __bfloat162float(hv));
        }
        size_t off = ((size_t)((z * 16 + (k0 >> 6)) * EMBED + n)) * 128 + ((c ^ (n & 7)) << 4);
        *(uint4*)((char*)g_wp_h + off) = H.q;
        *(uint4*)((char*)g_wp_l + off) = L.q;
    }
}

// ================= attention (bulk 2-stage) =================
#define ASTG 32768
#define SMEM_AT (32768 + 2*ASTG)    /* Qh|Ql 32K + 2 stages = 96K */

__device__ __forceinline__ void a_issue(uint32_t sbase, uint32_t mb0, int kt, int n)
{
    uint32_t mb = mb0 + (uint32_t)(kt & 1) * 8;
    uint32_t sb = sbase + 32768 + (uint32_t)(kt & 1) * ASTG;
    size_t off = ((size_t)(n * SP + kt * 64)) * 128;
    MBAR_EXPECT(mb, 32768);
    BULK_G2S(sb,         (const char*)g_kp_h + off, 8192, mb);
    BULK_G2S(sb + 8192,  (const char*)g_kp_l + off, 8192, mb);
    BULK_G2S(sb + 16384, (const char*)g_vp_h + off, 8192, mb);
    BULK_G2S(sb + 24576, (const char*)g_vp_l + off, 8192, mb);
}

__global__ __launch_bounds__(256, 1)
void attn_kernel()
{
    extern __shared__ __align__(128) char smem[];
    __shared__ uint64_t ambars[3];
    const uint32_t sbase = smem_u32(smem), mb0 = smem_u32(ambars);
    const int tid = threadIdx.x, lane = tid & 31, w = tid >> 5;
    const int n = blockIdx.y, Q0 = blockIdx.x * 128;
    const int lr = lane & 7, mat = lane >> 3;
    const int a_roff = (mat & 1) * 8 + lr;
    const int b_roff = (mat >> 1) * 8 + lr;
    const int v_roff = (mat & 1) * 8 + lr;

    if (tid == 0) { MBAR_INIT(mb0, 1); MBAR_INIT(mb0 + 8, 1); MBAR_INIT(mb0 + 16, 1); }
    __syncthreads();
    if (tid == 0) {
        size_t oq = ((size_t)(n * SP + Q0)) * 128;
        MBAR_EXPECT(mb0 + 16, 32768);
        BULK_G2S(sbase,         (const char*)g_qp_h + oq, 16384, mb0 + 16);
        BULK_G2S(sbase + 16384, (const char*)g_qp_l + oq, 16384, mb0 + 16);
        a_issue(sbase, mb0, 0, n);
        a_issue(sbase, mb0, 1, n);
    }
    MBAR_WAIT(mb0 + 16, 0);

    float Sv[8][4], O[8][4];
    float m1 = -CUDART_INF_F, m2 = -CUDART_INF_F, l1 = 0.f, l2 = 0.f;
    #pragma unroll
    for (int t = 0; t < 8; t++)
        #pragma unroll
        for (int r = 0; r < 4; r++) O[t][r] = 0.f;

    for (int kt = 0; kt < SP / 64; kt++) {
        MBAR_WAIT(mb0 + (uint32_t)(kt & 1) * 8, (kt >> 1) & 1);
        const uint32_t kb = sbase + 32768 + (uint32_t)(kt & 1) * ASTG;

        #pragma unroll
        for (int t = 0; t < 8; t++)
            #pragma unroll
            for (int r = 0; r < 4; r++) Sv[t][r] = 0.f;

        #pragma unroll
        for (int k4 = 0; k4 < 4; k4++) {
            uint32_t aqh[4], aql[4];
            {
                int r = w * 16 + a_roff;
                int ck = k4 * 2 + (mat >> 1);
                uint32_t qa = sbase + (uint32_t)(r * 128 + ((ck ^ (r & 7)) << 4));
                LDMX4(aqh[0], aqh[1], aqh[2], aqh[3], qa);
                LDMX4(aql[0], aql[1], aql[2], aql[3], qa + 16384);
            }
            uint32_t khf[8][2], klf[8][2];
            #pragma unroll
            for (int g = 0; g < 4; g++) {
                int rk = g * 16 + b_roff;
                int ck = k4 * 2 + (mat & 1);
                uint32_t ka = kb + (uint32_t)(rk * 128 + ((ck ^ (rk & 7)) << 4));
                LDMX4(khf[2*g][0], khf[2*g][1], khf[2*g+1][0], khf[2*g+1][1], ka);
                LDMX4(klf[2*g][0], klf[2*g][1], klf[2*g+1][0], klf[2*g+1][1], ka + 8192);
            }
            #pragma unroll
            for (int t = 0; t < 8; t++) {
                mma16816(Sv[t], aqh, khf[t]);
                mma16816(Sv[t], aqh, klf[t]);
                mma16816(Sv[t], aql, khf[t]);
            }
        }

        float mx1 = -CUDART_INF_F, mx2 = -CUDART_INF_F;
        #pragma unroll
        for (int t = 0; t < 8; t++) {
            mx1 = fmaxf(mx1, fmaxf(Sv[t][0], Sv[t][1]));
            mx2 = fmaxf(mx2, fmaxf(Sv[t][2], Sv[t][3]));
        }
        mx1 = fmaxf(mx1, __shfl_xor_sync(0xffffffffu, mx1, 1));
        mx1 = fmaxf(mx1, __shfl_xor_sync(0xffffffffu, mx1, 2));
        mx2 = fmaxf(mx2, __shfl_xor_sync(0xffffffffu, mx2, 1));
        mx2 = fmaxf(mx2, __shfl_xor_sync(0xffffffffu, mx2, 2));
        float mn1 = fmaxf(m1, mx1), mn2 = fmaxf(m2, mx2);
        float al1 = __expf(m1 - mn1), al2 = __expf(m2 - mn2);
        m1 = mn1; m2 = mn2;
        float rs1 = 0.f, rs2 = 0.f;
        #pragma unroll
        for (int t = 0; t < 8; t++) {
            Sv[t][0] = __expf(Sv[t][0] - mn1);
            Sv[t][1] = __expf(Sv[t][1] - mn1);
            Sv[t][2] = __expf(Sv[t][2] - mn2);
            Sv[t][3] = __expf(Sv[t][3] - mn2);
            rs1 += Sv[t][0] + Sv[t][1];
            rs2 += Sv[t][2] + Sv[t][3];
        }
        rs1 += __shfl_xor_sync(0xffffffffu, rs1, 1);
        rs1 += __shfl_xor_sync(0xffffffffu, rs1, 2);
        rs2 += __shfl_xor_sync(0xffffffffu, rs2, 1);
        rs2 += __shfl_xor_sync(0xffffffffu, rs2, 2);
        l1 = l1 * al1 + rs1;
        l2 = l2 * al2 + rs2;
        #pragma unroll
        for (int t = 0; t < 8; t++) {
            O[t][0] *= al1; O[t][1] *= al1;
            O[t][2] *= al2; O[t][3] *= al2;
        }

        #pragma unroll
        for (int jj = 0; jj < 4; jj++) {
            uint32_t ph[4], pl[4];
            pack_split(Sv[2*jj][0],   Sv[2*jj][1],   ph[0], pl[0]);
            pack_split(Sv[2*jj][2],   Sv[2*jj][3],   ph[1], pl[1]);
            pack_split(Sv[2*jj+1][0], Sv[2*jj+1][1], ph[2], pl[2]);
            pack_split(Sv[2*jj+1][2], Sv[2*jj+1][3], ph[3], pl[3]);
            uint32_t vhf[8][2], vlf[8][2];
            #pragma unroll
            for (int g = 0; g < 4; g++) {
                int rv = jj * 16 + v_roff;
                int ck = g * 2 + (mat >> 1);
                uint32_t va = kb + 16384 + (uint32_t)(rv * 128 + ((ck ^ (rv & 7)) << 4));
                LDMX4T(vhf[2*g][0], vhf[2*g][1], vhf[2*g+1][0], vhf[2*g+1][1], va);
                LDMX4T(vlf[2*g][0], vlf[2*g][1], vlf[2*g+1][0], vlf[2*g+1][1], va + 8192);
            }
            #pragma unroll
            for (int t = 0; t < 8; t++) {
                mma16816(O[t], ph, vhf[t]);
                mma16816(O[t], ph, vlf[t]);
                mma16816(O[t], pl, vhf[t]);
            }
        }
        __syncthreads();
        if (tid == 0 && kt + 2 < SP / 64) a_issue(sbase, mb0, kt + 2, n);
    }

    // epilogue: /l, q-pair maxpool, write packed out-GEMM A operand
    const float inv1 = 1.f / l1, inv2 = 1.f / l2;
    const int prow1 = Q0 / 2 + w * 8 + (lane >> 3);
    const int prow2 = prow1 + 4;
    #pragma unroll
    for (int t = 0; t < 8; t++) {
        float o0 = O[t][0] * inv1, o1 = O[t][1] * inv1;
        float o2 = O[t][2] * inv2, o3 = O[t][3] * inv2;
        float p0 = __shfl_xor_sync(0xffffffffu, o0, 4);
        float p1 = __shfl_xor_sync(0xffffffffu, o1, 4);
        float p2 = __shfl_xor_sync(0xffffffffu, o2, 4);
        float p3 = __shfl_xor_sync(0xffffffffu, o3, 4);
        if ((lane & 4) == 0) {
            int d = t * 8 + (lane & 3) * 2;
            uint32_t h0, l0, h1, l1u;
            pack_split(fmaxf(o0, p0), fmaxf(o1, p1), h0, l0);
            pack_split(fmaxf(o2, p2), fmaxf(o3, p3), h1, l1u);
            int mrow1 = n * 64 + (prow1 >> 4), kc1 = prow1 & 15;
            int mrow2 = n * 64 + (prow2 >> 4), kc2 = prow2 & 15;
            size_t a0 = ((size_t)(kc1 * 4096 + mrow1)) * 128
                      + (((d >> 3) ^ (mrow1 & 7)) << 4) + ((d & 7) << 1);
            size_t a1 = ((size_t)(kc2 * 4096 + mrow2)) * 128
                      + (((d >> 3) ^ (mrow2 & 7)) << 4) + ((d & 7) << 1);
            *(uint32_t*)((char*)g_ap_h + a0) = h0;
            *(uint32_t*)((char*)g_ap_l + a0) = l0;
            *(uint32_t*)((char*)g_ap_h + a1) = h1;
            *(uint32_t*)((char*)g_ap_l + a1) = l1u;
        }
    }
}

// ---------------- launch ----------------
extern "C" void kernel_launch(void* const* d_in, const int* in_sizes, int n_in,
                              void* d_out, int out_size)
{
    const float* x  = (const float*)d_in[0];
    const float* Wq = (const float*)d_in[1];
    const float* bq = (const float*)d_in[2];
    const float* Wk = (const float*)d_in[3];
    const float* bk = (const float*)d_in[4];
    const float* Wv = (const float*)d_in[5];
    const float* bv = (const float*)d_in[6];
    const float* Wo = (const float*)d_in[7];
    const float* bo = (const float*)d_in[8];
    float* out = (float*)d_out;

    cudaFuncSetAttribute(qkv_hmma_kernel, cudaFuncAttributeMaxDynamicSharedMemorySize, SMEM_GM);
    cudaFuncSetAttribute(out_hmma_kernel, cudaFuncAttributeMaxDynamicSharedMemorySize, SMEM_GM);
    cudaFuncSetAttribute(attn_kernel,     cudaFuncAttributeMaxDynamicSharedMemorySize, SMEM_AT);

    conv_x_kernel<<<(M_QKV * EMBED / 8) / 256, 256>>>(x);
    conv_w_kernel<<<dim3(16, 16, 4), 256>>>(Wq, Wk, Wv, Wo);

    qkv_hmma_kernel<<<dim3(EMBED / 128, M_QKV / 128, 3), 256, SMEM_GM>>>(bq, bk, bv);

    attn_kernel<<<dim3(SP / 128, NPOOL), 256, SMEM_AT>>>();

    out_hmma_kernel<<<dim3(EMBED / 128, 4 * SQ4 / 128), 256, SMEM_GM>>>(bo, out);
}